// round 1
// baseline (speedup 1.0000x reference)
#include <cuda_runtime.h>
#include <cuda_bf16.h>
#include <math.h>

// Problem constants
#define NB 4
#define NN 8192
#define KNN 16
#define DM 64
#define NPTS (NB * NN)   // 32768

// -------- device scratch (no dynamic allocation allowed) --------
__device__ float g_QKV[3][(size_t)NPTS * DM];   // Q, XK, XV  (25 MB)
__device__ float g_Wf[3][DM * DM];              // folded fc1@{wq,wk,wv}
__device__ float g_bf[3][DM];                   // folded fc1_b@{wq,wk,wv}

// ================= Kernel 0: fold fc1 into wq/wk/wv =================
__global__ void fold_kernel(const float* __restrict__ fc1_w,
                            const float* __restrict__ fc1_b,
                            const float* __restrict__ wq,
                            const float* __restrict__ wk,
                            const float* __restrict__ wv) {
    const float* Ws[3] = {wq, wk, wv};
    int t = blockIdx.x * blockDim.x + threadIdx.x;
    int total = 3 * DM * (DM + 1);  // 3 * (64*64 weights + 64 bias)
    for (int o = t; o < total; o += gridDim.x * blockDim.x) {
        int w = o / (DM * (DM + 1));
        int r = o % (DM * (DM + 1));
        const float* W = Ws[w];
        if (r < DM * DM) {
            int c = r >> 6, f = r & 63;
            float acc = 0.f;
            #pragma unroll 8
            for (int m = 0; m < DM; m++) acc = fmaf(fc1_w[c * DM + m], W[m * DM + f], acc);
            g_Wf[w][c * DM + f] = acc;
        } else {
            int f = r - DM * DM;
            float acc = 0.f;
            #pragma unroll 8
            for (int m = 0; m < DM; m++) acc = fmaf(fc1_b[m], W[m * DM + f], acc);
            g_bf[w][f] = acc;
        }
    }
}

// ================= Kernel 1: Q / XK / XV GEMMs =================
// grid: (NPTS/64, 3), block: 256.  Each block: 64 rows x 64 cols of output w.
__global__ __launch_bounds__(256) void qkv_kernel(const float* __restrict__ features) {
    __shared__ float in_sh[64][64];
    __shared__ float W_sh[64][64];
    __shared__ float b_sh[64];

    const int w = blockIdx.y;
    const int row0 = blockIdx.x * 64;
    const int tid = threadIdx.x;

    for (int i = tid; i < 4096; i += 256) W_sh[i >> 6][i & 63] = g_Wf[w][i];
    if (tid < 64) b_sh[tid] = g_bf[w][tid];
    {
        const float4* fin = (const float4*)(features + (size_t)row0 * DM);
        float4* in4 = (float4*)&in_sh[0][0];
        for (int i = tid; i < 1024; i += 256) in4[i] = fin[i];
    }
    __syncthreads();

    const int col = tid & 63;
    const int rg = tid >> 6;  // 0..3, each handles 16 rows
    float acc[16];
    #pragma unroll
    for (int r = 0; r < 16; r++) acc[r] = b_sh[col];

    #pragma unroll
    for (int c = 0; c < 64; c += 4) {
        float w0 = W_sh[c + 0][col];
        float w1 = W_sh[c + 1][col];
        float w2 = W_sh[c + 2][col];
        float w3 = W_sh[c + 3][col];
        #pragma unroll
        for (int r = 0; r < 16; r++) {
            float4 x = *(const float4*)&in_sh[rg * 16 + r][c];
            float a = acc[r];
            a = fmaf(x.x, w0, a);
            a = fmaf(x.y, w1, a);
            a = fmaf(x.z, w2, a);
            a = fmaf(x.w, w3, a);
            acc[r] = a;
        }
    }

    float* outp = g_QKV[w];
    #pragma unroll
    for (int r = 0; r < 16; r++)
        outp[(size_t)(row0 + rg * 16 + r) * DM + col] = acc[r];
}

// ================= Kernel 2: fused per-point transformer =================
struct SM2 {
    float d2[4096];
    float g1[4096];
    float g2[4096];
    float fc2[4096];
    float d1[192];
    float d1b[64], d2b[64], g1b[64], g2b[64], fc2b[64];
    float bufA[2][16][64];   // k, then u
    float bufB[2][16][64];   // t, then h, then a
    float pos[2][16][64];
    float vsh[2][16][64];
    float qsh[2][64];
    float res[2][64];
    float xyzc[2][4];
    float rel[2][16][4];
    int   idxs[2][16];
};

// warp computes 4 rows of out = in @ W + b.  in/out: row stride 64, base at row j0.
// MODE: 0 = none, 1 = relu, 2 = scale by 1/8
template <int MODE>
__device__ __forceinline__ void warp_matvec4(const float* __restrict__ Wsh,
                                             const float* __restrict__ bsh,
                                             const float* __restrict__ in,
                                             float* __restrict__ outp,
                                             int l) {
    float accx[4], accy[4];
    const float bx = bsh[2 * l], by = bsh[2 * l + 1];
    #pragma unroll
    for (int r = 0; r < 4; r++) { accx[r] = bx; accy[r] = by; }

    #pragma unroll
    for (int c = 0; c < 64; c += 4) {
        float2 w0 = *(const float2*)(Wsh + (c + 0) * 64 + 2 * l);
        float2 w1 = *(const float2*)(Wsh + (c + 1) * 64 + 2 * l);
        float2 w2 = *(const float2*)(Wsh + (c + 2) * 64 + 2 * l);
        float2 w3 = *(const float2*)(Wsh + (c + 3) * 64 + 2 * l);
        #pragma unroll
        for (int r = 0; r < 4; r++) {
            float4 x = *(const float4*)(in + r * 64 + c);
            float ax = accx[r], ay = accy[r];
            ax = fmaf(x.x, w0.x, ax);
            ax = fmaf(x.y, w1.x, ax);
            ax = fmaf(x.z, w2.x, ax);
            ax = fmaf(x.w, w3.x, ax);
            ay = fmaf(x.x, w0.y, ay);
            ay = fmaf(x.y, w1.y, ay);
            ay = fmaf(x.z, w2.y, ay);
            ay = fmaf(x.w, w3.y, ay);
            accx[r] = ax; accy[r] = ay;
        }
    }
    #pragma unroll
    for (int r = 0; r < 4; r++) {
        float vx = accx[r], vy = accy[r];
        if (MODE == 1) { vx = fmaxf(vx, 0.f); vy = fmaxf(vy, 0.f); }
        if (MODE == 2) { vx *= 0.125f; vy *= 0.125f; }
        outp[r * 64 + 2 * l] = vx;
        outp[r * 64 + 2 * l + 1] = vy;
    }
}

__global__ __launch_bounds__(256, 2) void main_kernel(
    const float* __restrict__ xyz, const float* __restrict__ features,
    const int* __restrict__ knn,
    const float* __restrict__ d1w, const float* __restrict__ d1b,
    const float* __restrict__ d2w, const float* __restrict__ d2b,
    const float* __restrict__ g1w, const float* __restrict__ g1b,
    const float* __restrict__ g2w, const float* __restrict__ g2b,
    const float* __restrict__ fc2w, const float* __restrict__ fc2b,
    float* __restrict__ out) {
    extern __shared__ unsigned char smraw[];
    SM2& s = *reinterpret_cast<SM2*>(smraw);
    const int tid = threadIdx.x;

    // phase 0: load weights once per block
    for (int i = tid; i < 4096; i += 256) {
        s.d2[i] = d2w[i];
        s.g1[i] = g1w[i];
        s.g2[i] = g2w[i];
        s.fc2[i] = fc2w[i];
    }
    for (int i = tid; i < 192; i += 256) s.d1[i] = d1w[i];
    if (tid < 64) {
        s.d1b[tid] = d1b[tid]; s.d2b[tid] = d2b[tid];
        s.g1b[tid] = g1b[tid]; s.g2b[tid] = g2b[tid];
        s.fc2b[tid] = fc2b[tid];
    }
    __syncthreads();

    const int p = tid >> 7;          // point within block (0..1)
    const int pt = tid & 127;        // thread within point
    const int wp = (tid >> 5) & 3;   // warp within point (0..3)
    const int l = tid & 31;          // lane
    const int j0 = wp * 4;           // first of this warp's 4 neighbor rows
    float* __restrict__ attn_out = out + (size_t)NPTS * DM;

    for (int pair = blockIdx.x; pair < NPTS / 2; pair += gridDim.x) {
        const int m = pair * 2 + p;
        const int b = m >> 13;       // batch (N = 8192 = 2^13)

        // phase 1a: indices, center xyz, q
        if (pt < 16) s.idxs[p][pt] = knn[(size_t)m * KNN + pt];
        if (pt >= 16 && pt < 19) s.xyzc[p][pt - 16] = xyz[(size_t)m * 3 + (pt - 16)];
        if (pt >= 32 && pt < 96) s.qsh[p][pt - 32] = g_QKV[0][(size_t)m * DM + (pt - 32)];
        __syncthreads();

        // phase 1b: rel vectors + gather k,v rows
        if (pt < 16) {
            int iv = s.idxs[p][pt];
            const float* xr = xyz + (size_t)(b * NN + iv) * 3;
            s.rel[p][pt][0] = s.xyzc[p][0] - xr[0];
            s.rel[p][pt][1] = s.xyzc[p][1] - xr[1];
            s.rel[p][pt][2] = s.xyzc[p][2] - xr[2];
        }
        #pragma unroll
        for (int r = 0; r < 4; r++) {
            int j = j0 + r;
            int iv = s.idxs[p][j];
            const float2* kr = (const float2*)(g_QKV[1] + (size_t)(b * NN + iv) * DM);
            *(float2*)&s.bufA[p][j][2 * l] = kr[l];
            const float2* vr = (const float2*)(g_QKV[2] + (size_t)(b * NN + iv) * DM);
            *(float2*)&s.vsh[p][j][2 * l] = vr[l];
        }
        __syncthreads();

        // phase 2: t = relu(rel @ d1 + d1b) -> bufB (own rows)
        #pragma unroll
        for (int r = 0; r < 4; r++) {
            int j = j0 + r;
            float r0 = s.rel[p][j][0], r1 = s.rel[p][j][1], r2 = s.rel[p][j][2];
            #pragma unroll
            for (int h = 0; h < 2; h++) {
                int ch = 2 * l + h;
                float t = s.d1b[ch];
                t = fmaf(r0, s.d1[ch], t);
                t = fmaf(r1, s.d1[64 + ch], t);
                t = fmaf(r2, s.d1[128 + ch], t);
                s.bufB[p][j][ch] = fmaxf(t, 0.f);
            }
        }
        __syncwarp();
        // phase 2b: pos = t @ d2 + d2b
        warp_matvec4<0>(s.d2, s.d2b, &s.bufB[p][j0][0], &s.pos[p][j0][0], l);
        __syncwarp();
        // phase 3: h = q - k + pos -> bufB
        #pragma unroll
        for (int r = 0; r < 4; r++) {
            int j = j0 + r;
            #pragma unroll
            for (int h = 0; h < 2; h++) {
                int ch = 2 * l + h;
                s.bufB[p][j][ch] = s.qsh[p][ch] - s.bufA[p][j][ch] + s.pos[p][j][ch];
            }
        }
        __syncwarp();
        // phase 4: u = relu(h @ g1 + g1b) -> bufA
        warp_matvec4<1>(s.g1, s.g1b, &s.bufB[p][j0][0], &s.bufA[p][j0][0], l);
        __syncwarp();
        // phase 5: a = (u @ g2 + g2b) / 8 -> bufB
        warp_matvec4<2>(s.g2, s.g2b, &s.bufA[p][j0][0], &s.bufB[p][j0][0], l);
        __syncthreads();

        // phase 6: per-channel softmax over 16 neighbors + weighted sum
        if (pt < 64) {
            const int f = pt;
            float av[16];
            float mx = -3.4e38f;
            #pragma unroll
            for (int j = 0; j < KNN; j++) {
                av[j] = s.bufB[p][j][f];
                mx = fmaxf(mx, av[j]);
            }
            float ssum = 0.f;
            #pragma unroll
            for (int j = 0; j < KNN; j++) {
                av[j] = __expf(av[j] - mx);
                ssum += av[j];
            }
            float inv = 1.f / ssum;
            float racc = 0.f;
            float* ab = attn_out + (size_t)m * KNN * DM + f;
            #pragma unroll
            for (int j = 0; j < KNN; j++) {
                float a = av[j] * inv;
                ab[(size_t)j * DM] = a;
                racc = fmaf(a, s.vsh[p][j][f] + s.pos[p][j][f], racc);
            }
            s.res[p][f] = racc;
        }
        __syncthreads();

        // phase 7: out = res @ fc2 + fc2_b + features
        if (pt < 64) {
            const int f = pt;
            float acc = s.fc2b[f];
            #pragma unroll
            for (int c = 0; c < 64; c++)
                acc = fmaf(s.res[p][c], s.fc2[c * 64 + f], acc);
            out[(size_t)m * DM + f] = acc + features[(size_t)m * DM + f];
        }
        __syncthreads();
    }
}

// ================= launch =================
extern "C" void kernel_launch(void* const* d_in, const int* in_sizes, int n_in,
                              void* d_out, int out_size) {
    const float* xyz      = (const float*)d_in[0];
    const float* features = (const float*)d_in[1];
    const int*   knn      = (const int*)d_in[2];
    const float* fc1_w    = (const float*)d_in[3];
    const float* fc1_b    = (const float*)d_in[4];
    const float* fc2_w    = (const float*)d_in[5];
    const float* fc2_b    = (const float*)d_in[6];
    const float* d1_w     = (const float*)d_in[7];
    const float* d1_b     = (const float*)d_in[8];
    const float* d2_w     = (const float*)d_in[9];
    const float* d2_b     = (const float*)d_in[10];
    const float* g1_w     = (const float*)d_in[11];
    const float* g1_b     = (const float*)d_in[12];
    const float* g2_w     = (const float*)d_in[13];
    const float* g2_b     = (const float*)d_in[14];
    const float* wq       = (const float*)d_in[15];
    const float* wk       = (const float*)d_in[16];
    const float* wv       = (const float*)d_in[17];
    float* out = (float*)d_out;

    fold_kernel<<<49, 256>>>(fc1_w, fc1_b, wq, wk, wv);
    qkv_kernel<<<dim3(NPTS / 64, 3), 256>>>(features);

    cudaFuncSetAttribute(main_kernel, cudaFuncAttributeMaxDynamicSharedMemorySize,
                         (int)sizeof(SM2));
    main_kernel<<<304, 256, sizeof(SM2)>>>(xyz, features, knn,
                                           d1_w, d1_b, d2_w, d2_b,
                                           g1_w, g1_b, g2_w, g2_b,
                                           fc2_w, fc2_b, out);
}

// round 2
// speedup vs baseline: 1.5809x; 1.5809x over previous
#include <cuda_runtime.h>
#include <math.h>

// Problem constants
#define NB 4
#define NN 8192
#define KNN 16
#define DM 64
#define NPTS (NB * NN)   // 32768

typedef unsigned long long ull;

// -------- device scratch (no dynamic allocation allowed) --------
__device__ float g_QKV[3][(size_t)NPTS * DM];   // Q, XK, XV
__device__ float g_Wf[3][DM * DM];              // folded fc1@{wq,wk,wv}
__device__ float g_bf[3][DM];                   // folded fc1_b@{wq,wk,wv}

// ---------------- f32x2 helpers ----------------
__device__ __forceinline__ ull pk2(float a, float b) {
    ull r; asm("mov.b64 %0,{%1,%2};" : "=l"(r) : "f"(a), "f"(b)); return r;
}
__device__ __forceinline__ void up2(ull p, float& a, float& b) {
    asm("mov.b64 {%0,%1},%2;" : "=f"(a), "=f"(b) : "l"(p));
}
__device__ __forceinline__ ull ffma2(ull a, ull b, ull c) {
    ull d; asm("fma.rn.f32x2 %0,%1,%2,%3;" : "=l"(d) : "l"(a), "l"(b), "l"(c));
    return d;
}

// ================= Kernel 0: fold fc1 into wq/wk/wv =================
__global__ void fold_kernel(const float* __restrict__ fc1_w,
                            const float* __restrict__ fc1_b,
                            const float* __restrict__ wq,
                            const float* __restrict__ wk,
                            const float* __restrict__ wv) {
    const float* Ws[3] = {wq, wk, wv};
    int t = blockIdx.x * blockDim.x + threadIdx.x;
    int total = 3 * DM * (DM + 1);
    for (int o = t; o < total; o += gridDim.x * blockDim.x) {
        int w = o / (DM * (DM + 1));
        int r = o % (DM * (DM + 1));
        const float* W = Ws[w];
        if (r < DM * DM) {
            int c = r >> 6, f = r & 63;
            float acc = 0.f;
            #pragma unroll 8
            for (int m = 0; m < DM; m++) acc = fmaf(fc1_w[c * DM + m], W[m * DM + f], acc);
            g_Wf[w][c * DM + f] = acc;
        } else {
            int f = r - DM * DM;
            float acc = 0.f;
            #pragma unroll 8
            for (int m = 0; m < DM; m++) acc = fmaf(fc1_b[m], W[m * DM + f], acc);
            g_bf[w][f] = acc;
        }
    }
}

// ================= Kernel 1: Q / XK / XV GEMMs =================
__global__ __launch_bounds__(256) void qkv_kernel(const float* __restrict__ features) {
    __shared__ float in_sh[64][64];
    __shared__ float W_sh[64][64];
    __shared__ float b_sh[64];

    const int w = blockIdx.y;
    const int row0 = blockIdx.x * 64;
    const int tid = threadIdx.x;

    for (int i = tid; i < 4096; i += 256) W_sh[i >> 6][i & 63] = g_Wf[w][i];
    if (tid < 64) b_sh[tid] = g_bf[w][tid];
    {
        const float4* fin = (const float4*)(features + (size_t)row0 * DM);
        float4* in4 = (float4*)&in_sh[0][0];
        for (int i = tid; i < 1024; i += 256) in4[i] = fin[i];
    }
    __syncthreads();

    const int col = tid & 63;
    const int rg = tid >> 6;
    float acc[16];
    #pragma unroll
    for (int r = 0; r < 16; r++) acc[r] = b_sh[col];

    #pragma unroll
    for (int c = 0; c < 64; c += 4) {
        float w0 = W_sh[c + 0][col];
        float w1 = W_sh[c + 1][col];
        float w2 = W_sh[c + 2][col];
        float w3 = W_sh[c + 3][col];
        #pragma unroll
        for (int r = 0; r < 16; r++) {
            float4 x = *(const float4*)&in_sh[rg * 16 + r][c];
            float a = acc[r];
            a = fmaf(x.x, w0, a);
            a = fmaf(x.y, w1, a);
            a = fmaf(x.z, w2, a);
            a = fmaf(x.w, w3, a);
            acc[r] = a;
        }
    }

    float* outp = g_QKV[w];
    #pragma unroll
    for (int r = 0; r < 16; r++)
        outp[(size_t)(row0 + rg * 16 + r) * DM + col] = acc[r];
}

// ================= Kernel 2: warp-per-point fused transformer =================
// Per-point smem: matvec input buffer in CHANNEL-MAJOR layout [64 ch][18 rows]
// so x-operand pairs across neighbor rows are natural 8-byte loads.
struct PtSm {
    float buf[64 * 18];   // 4608 B  (t -> h -> u, reused)
    float relT[3][16];    // transposed rel vectors
    float res[64];
    int   idx[16];
};
struct SMem {
    float w_d2[4096];
    float w_g1[4096];
    float w_g2[4096];
    float w_fc2[4096];
    float w_d1[192];
    float bias[5][64];    // d1b, d2b, g1b, g2b, fc2b
    PtSm  pt[8];
};

// Warp-wide matvec: out[16 rows][64 ch] = in[ch-major] @ W + b.
// Lane l owns output channels ch0=2l, ch1=2l+1 for ALL 16 rows.
// acc[p]   = (out[ch0][2p], out[ch0][2p+1])   p=0..7
// acc[8+p] = (out[ch1][2p], out[ch1][2p+1])
__device__ __forceinline__ void wmv(const float* __restrict__ W,
                                    float bias0, float bias1,
                                    const float* __restrict__ in,
                                    int l, ull acc[16]) {
    ull B0 = pk2(bias0, bias0), B1 = pk2(bias1, bias1);
    #pragma unroll
    for (int p = 0; p < 8; p++) { acc[p] = B0; acc[8 + p] = B1; }

    #pragma unroll 8
    for (int c = 0; c < 64; c++) {
        const ull* col = reinterpret_cast<const ull*>(in + c * 18);
        float2 w = *reinterpret_cast<const float2*>(W + c * 64 + 2 * l);
        ull wx = pk2(w.x, w.x);
        ull wy = pk2(w.y, w.y);
        #pragma unroll
        for (int p = 0; p < 8; p++) {
            ull x = col[p];          // (in[2p][c], in[2p+1][c]) — broadcast LDS.64
            acc[p]     = ffma2(x, wx, acc[p]);
            acc[8 + p] = ffma2(x, wy, acc[8 + p]);
        }
    }
}

__global__ __launch_bounds__(256, 2) void main_kernel(
    const float* __restrict__ xyz, const float* __restrict__ features,
    const int* __restrict__ knn,
    const float* __restrict__ d1w, const float* __restrict__ d1b,
    const float* __restrict__ d2w, const float* __restrict__ d2b,
    const float* __restrict__ g1w, const float* __restrict__ g1b,
    const float* __restrict__ g2w, const float* __restrict__ g2b,
    const float* __restrict__ fc2w, const float* __restrict__ fc2b,
    float* __restrict__ out) {
    extern __shared__ unsigned char smraw[];
    SMem& s = *reinterpret_cast<SMem*>(smraw);
    const int tid = threadIdx.x;

    // phase 0: stage weights once per block
    for (int i = tid; i < 4096; i += 256) {
        s.w_d2[i] = d2w[i];
        s.w_g1[i] = g1w[i];
        s.w_g2[i] = g2w[i];
        s.w_fc2[i] = fc2w[i];
    }
    for (int i = tid; i < 192; i += 256) s.w_d1[i] = d1w[i];
    if (tid < 64) {
        s.bias[0][tid] = d1b[tid];
        s.bias[1][tid] = d2b[tid];
        s.bias[2][tid] = g1b[tid];
        s.bias[3][tid] = g2b[tid];
        s.bias[4][tid] = fc2b[tid];
    }
    __syncthreads();

    const int wp = tid >> 5;   // warp = point slot (0..7)
    const int l  = tid & 31;   // lane; owns channels 2l, 2l+1
    PtSm& p = s.pt[wp];
    const float* __restrict__ Qb = g_QKV[0];
    const float* __restrict__ Kb = g_QKV[1];
    const float* __restrict__ Vb = g_QKV[2];
    float* __restrict__ attn_out = out + (size_t)NPTS * DM;

    for (int m = blockIdx.x * 8 + wp; m < NPTS; m += gridDim.x * 8) {
        const int b = m >> 13;   // batch (NN = 8192)

        // --- indices + rel vectors (lanes 0..15) ---
        if (l < 16) {
            int nb = knn[(size_t)m * KNN + l];
            p.idx[l] = nb;
            const float* xr = xyz + (size_t)(b * NN + nb) * 3;
            const float* xc = xyz + (size_t)m * 3;
            p.relT[0][l] = xc[0] - xr[0];
            p.relT[1][l] = xc[1] - xr[1];
            p.relT[2][l] = xc[2] - xr[2];
        }
        float2 q = *(const float2*)(Qb + (size_t)m * DM + 2 * l);
        __syncwarp();

        // --- t = relu(rel @ d1 + d1b), channel-major into buf ---
        {
            float2 dw0 = *(const float2*)(s.w_d1 + 2 * l);
            float2 dw1 = *(const float2*)(s.w_d1 + 64 + 2 * l);
            float2 dw2 = *(const float2*)(s.w_d1 + 128 + 2 * l);
            float2 db  = *(const float2*)(&s.bias[0][2 * l]);
            float* b0 = p.buf + (2 * l) * 18;
            float* b1 = p.buf + (2 * l + 1) * 18;
            #pragma unroll
            for (int j = 0; j < 16; j++) {
                float r0 = p.relT[0][j], r1 = p.relT[1][j], r2 = p.relT[2][j];
                float t0 = fmaf(r2, dw2.x, fmaf(r1, dw1.x, fmaf(r0, dw0.x, db.x)));
                float t1 = fmaf(r2, dw2.y, fmaf(r1, dw1.y, fmaf(r0, dw0.y, db.y)));
                b0[j] = fmaxf(t0, 0.f);
                b1[j] = fmaxf(t1, 0.f);
            }
        }
        __syncwarp();

        // --- pos = t @ d2 + d2b  (register-resident pairs) ---
        ull acc[16];
        {
            float2 bb = *(const float2*)(&s.bias[1][2 * l]);
            wmv(s.w_d2, bb.x, bb.y, p.buf, l, acc);
        }
        float pos0[16], pos1[16];
        #pragma unroll
        for (int pp = 0; pp < 8; pp++) {
            up2(acc[pp],     pos0[2 * pp], pos0[2 * pp + 1]);
            up2(acc[8 + pp], pos1[2 * pp], pos1[2 * pp + 1]);
        }

        // --- gather k rows (register-resident) ---
        float2 kr[16];
        #pragma unroll
        for (int j = 0; j < 16; j++) {
            int nb = p.idx[j];
            kr[j] = *(const float2*)(Kb + ((size_t)(b * NN) + nb) * DM + 2 * l);
        }
        __syncwarp();   // all lanes finished reading t from buf

        // --- h = q - k + pos, channel-major into buf ---
        {
            float* b0 = p.buf + (2 * l) * 18;
            float* b1 = p.buf + (2 * l + 1) * 18;
            #pragma unroll
            for (int j = 0; j < 16; j++) {
                b0[j] = q.x - kr[j].x + pos0[j];
                b1[j] = q.y - kr[j].y + pos1[j];
            }
        }
        __syncwarp();

        // --- u = relu(h @ g1 + g1b) ---
        {
            float2 bb = *(const float2*)(&s.bias[2][2 * l]);
            wmv(s.w_g1, bb.x, bb.y, p.buf, l, acc);
        }
        __syncwarp();   // all lanes finished reading h before overwriting
        {
            float* b0 = p.buf + (2 * l) * 18;
            float* b1 = p.buf + (2 * l + 1) * 18;
            #pragma unroll
            for (int pp = 0; pp < 8; pp++) {
                float u0, u1, u2, u3;
                up2(acc[pp], u0, u1);
                up2(acc[8 + pp], u2, u3);
                *(float2*)(b0 + 2 * pp) = make_float2(fmaxf(u0, 0.f), fmaxf(u1, 0.f));
                *(float2*)(b1 + 2 * pp) = make_float2(fmaxf(u2, 0.f), fmaxf(u3, 0.f));
            }
        }
        __syncwarp();

        // --- logits = u @ g2 + g2b (stay in registers) ---
        {
            float2 bb = *(const float2*)(&s.bias[3][2 * l]);
            wmv(s.w_g2, bb.x, bb.y, p.buf, l, acc);
        }

        // --- gather v rows (latency overlapped with softmax) ---
        float2 vr[16];
        #pragma unroll
        for (int j = 0; j < 16; j++) {
            int nb = p.idx[j];
            vr[j] = *(const float2*)(Vb + ((size_t)(b * NN) + nb) * DM + 2 * l);
        }

        // --- softmax over 16 neighbors, per channel, in registers ---
        float a0[16], a1[16];
        #pragma unroll
        for (int pp = 0; pp < 8; pp++) {
            up2(acc[pp],     a0[2 * pp], a0[2 * pp + 1]);
            up2(acc[8 + pp], a1[2 * pp], a1[2 * pp + 1]);
        }
        float mx0 = a0[0], mx1 = a1[0];
        #pragma unroll
        for (int j = 1; j < 16; j++) { mx0 = fmaxf(mx0, a0[j]); mx1 = fmaxf(mx1, a1[j]); }
        float sm0 = 0.f, sm1 = 0.f;
        #pragma unroll
        for (int j = 0; j < 16; j++) {
            a0[j] = __expf((a0[j] - mx0) * 0.125f); sm0 += a0[j];
            a1[j] = __expf((a1[j] - mx1) * 0.125f); sm1 += a1[j];
        }
        float inv0 = 1.f / sm0, inv1 = 1.f / sm1;

        // --- attn write + weighted sum ---
        float* ao = attn_out + (size_t)m * (KNN * DM) + 2 * l;
        float r0acc = 0.f, r1acc = 0.f;
        #pragma unroll
        for (int j = 0; j < 16; j++) {
            float w0 = a0[j] * inv0, w1 = a1[j] * inv1;
            *(float2*)(ao + (size_t)j * DM) = make_float2(w0, w1);
            r0acc = fmaf(w0, vr[j].x + pos0[j], r0acc);
            r1acc = fmaf(w1, vr[j].y + pos1[j], r1acc);
        }
        *(float2*)(&p.res[2 * l]) = make_float2(r0acc, r1acc);
        __syncwarp();

        // --- out = res @ fc2 + fc2_b + features ---
        {
            ull oacc = *(const ull*)(&s.bias[4][2 * l]);
            #pragma unroll 8
            for (int c = 0; c < 64; c++) {
                float rc = p.res[c];
                ull rp = pk2(rc, rc);
                ull w = *(const ull*)(s.w_fc2 + c * 64 + 2 * l);
                oacc = ffma2(rp, w, oacc);
            }
            float o0, o1; up2(oacc, o0, o1);
            float2 f = *(const float2*)(features + (size_t)m * DM + 2 * l);
            *(float2*)(out + (size_t)m * DM + 2 * l) = make_float2(o0 + f.x, o1 + f.y);
        }
        __syncwarp();   // res/buf WAR guard before next iteration
    }
}

// ================= launch =================
extern "C" void kernel_launch(void* const* d_in, const int* in_sizes, int n_in,
                              void* d_out, int out_size) {
    const float* xyz      = (const float*)d_in[0];
    const float* features = (const float*)d_in[1];
    const int*   knn      = (const int*)d_in[2];
    const float* fc1_w    = (const float*)d_in[3];
    const float* fc1_b    = (const float*)d_in[4];
    const float* fc2_w    = (const float*)d_in[5];
    const float* fc2_b    = (const float*)d_in[6];
    const float* d1_w     = (const float*)d_in[7];
    const float* d1_b     = (const float*)d_in[8];
    const float* d2_w     = (const float*)d_in[9];
    const float* d2_b     = (const float*)d_in[10];
    const float* g1_w     = (const float*)d_in[11];
    const float* g1_b     = (const float*)d_in[12];
    const float* g2_w     = (const float*)d_in[13];
    const float* g2_b     = (const float*)d_in[14];
    const float* wq       = (const float*)d_in[15];
    const float* wk       = (const float*)d_in[16];
    const float* wv       = (const float*)d_in[17];
    float* out = (float*)d_out;

    fold_kernel<<<49, 256>>>(fc1_w, fc1_b, wq, wk, wv);
    qkv_kernel<<<dim3(NPTS / 64, 3), 256>>>(features);

    cudaFuncSetAttribute(main_kernel, cudaFuncAttributeMaxDynamicSharedMemorySize,
                         (int)sizeof(SMem));
    main_kernel<<<296, 256, sizeof(SMem)>>>(xyz, features, knn,
                                            d1_w, d1_b, d2_w, d2_b,
                                            g1_w, g1_b, g2_w, g2_b,
                                            fc2_w, fc2_b, out);
}

// round 3
// speedup vs baseline: 1.5849x; 1.0026x over previous
#include <cuda_runtime.h>
#include <math.h>

// Problem constants
#define NB 4
#define NN 8192
#define KNN 16
#define DM 64
#define NPTS (NB * NN)   // 32768

typedef unsigned long long ull;

// -------- device scratch (no dynamic allocation allowed) --------
__device__ float g_QKV[3][(size_t)NPTS * DM];   // Q, XK, XV
__device__ float g_Wf[3][DM * DM];              // folded fc1@{wq,wk,wv}
__device__ float g_bf[3][DM];                   // folded fc1_b@{wq,wk,wv}

// ---------------- f32x2 helpers ----------------
__device__ __forceinline__ ull pk2(float a, float b) {
    ull r; asm("mov.b64 %0,{%1,%2};" : "=l"(r) : "f"(a), "f"(b)); return r;
}
__device__ __forceinline__ void up2(ull p, float& a, float& b) {
    asm("mov.b64 {%0,%1},%2;" : "=f"(a), "=f"(b) : "l"(p));
}
__device__ __forceinline__ ull ffma2(ull a, ull b, ull c) {
    ull d; asm("fma.rn.f32x2 %0,%1,%2,%3;" : "=l"(d) : "l"(a), "l"(b), "l"(c));
    return d;
}

// ================= Kernel 0: fold fc1 into wq/wk/wv =================
__global__ void fold_kernel(const float* __restrict__ fc1_w,
                            const float* __restrict__ fc1_b,
                            const float* __restrict__ wq,
                            const float* __restrict__ wk,
                            const float* __restrict__ wv) {
    const float* Ws[3] = {wq, wk, wv};
    int t = blockIdx.x * blockDim.x + threadIdx.x;
    int total = 3 * DM * (DM + 1);
    for (int o = t; o < total; o += gridDim.x * blockDim.x) {
        int w = o / (DM * (DM + 1));
        int r = o % (DM * (DM + 1));
        const float* W = Ws[w];
        if (r < DM * DM) {
            int c = r >> 6, f = r & 63;
            float acc = 0.f;
            #pragma unroll 8
            for (int m = 0; m < DM; m++) acc = fmaf(fc1_w[c * DM + m], W[m * DM + f], acc);
            g_Wf[w][c * DM + f] = acc;
        } else {
            int f = r - DM * DM;
            float acc = 0.f;
            #pragma unroll 8
            for (int m = 0; m < DM; m++) acc = fmaf(fc1_b[m], W[m * DM + f], acc);
            g_bf[w][f] = acc;
        }
    }
}

// ================= Kernel 1: Q / XK / XV GEMMs =================
__global__ __launch_bounds__(256) void qkv_kernel(const float* __restrict__ features) {
    __shared__ float in_sh[64][64];
    __shared__ float W_sh[64][64];
    __shared__ float b_sh[64];

    const int w = blockIdx.y;
    const int row0 = blockIdx.x * 64;
    const int tid = threadIdx.x;

    for (int i = tid; i < 4096; i += 256) W_sh[i >> 6][i & 63] = g_Wf[w][i];
    if (tid < 64) b_sh[tid] = g_bf[w][tid];
    {
        const float4* fin = (const float4*)(features + (size_t)row0 * DM);
        float4* in4 = (float4*)&in_sh[0][0];
        for (int i = tid; i < 1024; i += 256) in4[i] = fin[i];
    }
    __syncthreads();

    const int col = tid & 63;
    const int rg = tid >> 6;
    float acc[16];
    #pragma unroll
    for (int r = 0; r < 16; r++) acc[r] = b_sh[col];

    #pragma unroll
    for (int c = 0; c < 64; c += 4) {
        float w0 = W_sh[c + 0][col];
        float w1 = W_sh[c + 1][col];
        float w2 = W_sh[c + 2][col];
        float w3 = W_sh[c + 3][col];
        #pragma unroll
        for (int r = 0; r < 16; r++) {
            float4 x = *(const float4*)&in_sh[rg * 16 + r][c];
            float a = acc[r];
            a = fmaf(x.x, w0, a);
            a = fmaf(x.y, w1, a);
            a = fmaf(x.z, w2, a);
            a = fmaf(x.w, w3, a);
            acc[r] = a;
        }
    }

    float* outp = g_QKV[w];
    #pragma unroll
    for (int r = 0; r < 16; r++)
        outp[(size_t)(row0 + rg * 16 + r) * DM + col] = acc[r];
}

// ================= Kernel 2: warp-per-point fused transformer =================
// Per-point smem: matvec input buffer in CHANNEL-MAJOR layout [64 ch][18 rows]
// so x-operand pairs across neighbor rows are natural 8-byte loads.
struct PtSm {
    float buf[64 * 18];   // 4608 B  (t -> h -> u, reused)
    float relT[3][16];    // transposed rel vectors
    float res[64];
    int   idx[16];
};
struct SMem {
    float w_d2[4096];
    float w_g1[4096];
    float w_g2[4096];
    float w_fc2[4096];
    float w_d1[192];
    float bias[5][64];    // d1b, d2b, g1b, g2b, fc2b
    PtSm  pt[8];
};

// Warp-wide matvec: out[16 rows][64 ch] = in[ch-major] @ W + b.
// Lane l owns output channels ch0=2l, ch1=2l+1 for ALL 16 rows.
// acc[p]   = (out[ch0][2p], out[ch0][2p+1])   p=0..7
// acc[8+p] = (out[ch1][2p], out[ch1][2p+1])
__device__ __forceinline__ void wmv(const float* __restrict__ W,
                                    float bias0, float bias1,
                                    const float* __restrict__ in,
                                    int l, ull acc[16]) {
    ull B0 = pk2(bias0, bias0), B1 = pk2(bias1, bias1);
    #pragma unroll
    for (int p = 0; p < 8; p++) { acc[p] = B0; acc[8 + p] = B1; }

    #pragma unroll 8
    for (int c = 0; c < 64; c++) {
        const ull* col = reinterpret_cast<const ull*>(in + c * 18);
        float2 w = *reinterpret_cast<const float2*>(W + c * 64 + 2 * l);
        ull wx = pk2(w.x, w.x);
        ull wy = pk2(w.y, w.y);
        #pragma unroll
        for (int p = 0; p < 8; p++) {
            ull x = col[p];          // (in[2p][c], in[2p+1][c]) — broadcast LDS.64
            acc[p]     = ffma2(x, wx, acc[p]);
            acc[8 + p] = ffma2(x, wy, acc[8 + p]);
        }
    }
}

__global__ __launch_bounds__(256, 2) void main_kernel(
    const float* __restrict__ xyz, const float* __restrict__ features,
    const int* __restrict__ knn,
    const float* __restrict__ d1w, const float* __restrict__ d1b,
    const float* __restrict__ d2w, const float* __restrict__ d2b,
    const float* __restrict__ g1w, const float* __restrict__ g1b,
    const float* __restrict__ g2w, const float* __restrict__ g2b,
    const float* __restrict__ fc2w, const float* __restrict__ fc2b,
    float* __restrict__ out) {
    extern __shared__ unsigned char smraw[];
    SMem& s = *reinterpret_cast<SMem*>(smraw);
    const int tid = threadIdx.x;

    // phase 0: stage weights once per block
    for (int i = tid; i < 4096; i += 256) {
        s.w_d2[i] = d2w[i];
        s.w_g1[i] = g1w[i];
        s.w_g2[i] = g2w[i];
        s.w_fc2[i] = fc2w[i];
    }
    for (int i = tid; i < 192; i += 256) s.w_d1[i] = d1w[i];
    if (tid < 64) {
        s.bias[0][tid] = d1b[tid];
        s.bias[1][tid] = d2b[tid];
        s.bias[2][tid] = g1b[tid];
        s.bias[3][tid] = g2b[tid];
        s.bias[4][tid] = fc2b[tid];
    }
    __syncthreads();

    const int wp = tid >> 5;   // warp = point slot (0..7)
    const int l  = tid & 31;   // lane; owns channels 2l, 2l+1
    PtSm& p = s.pt[wp];
    const float* __restrict__ Qb = g_QKV[0];
    const float* __restrict__ Kb = g_QKV[1];
    const float* __restrict__ Vb = g_QKV[2];
    float* __restrict__ attn_out = out + (size_t)NPTS * DM;

    for (int m = blockIdx.x * 8 + wp; m < NPTS; m += gridDim.x * 8) {
        const int b = m >> 13;   // batch (NN = 8192)

        // --- indices + rel vectors (lanes 0..15) ---
        if (l < 16) {
            int nb = knn[(size_t)m * KNN + l];
            p.idx[l] = nb;
            const float* xr = xyz + (size_t)(b * NN + nb) * 3;
            const float* xc = xyz + (size_t)m * 3;
            p.relT[0][l] = xc[0] - xr[0];
            p.relT[1][l] = xc[1] - xr[1];
            p.relT[2][l] = xc[2] - xr[2];
        }
        float2 q = *(const float2*)(Qb + (size_t)m * DM + 2 * l);
        __syncwarp();

        // --- t = relu(rel @ d1 + d1b), channel-major into buf ---
        {
            float2 dw0 = *(const float2*)(s.w_d1 + 2 * l);
            float2 dw1 = *(const float2*)(s.w_d1 + 64 + 2 * l);
            float2 dw2 = *(const float2*)(s.w_d1 + 128 + 2 * l);
            float2 db  = *(const float2*)(&s.bias[0][2 * l]);
            float* b0 = p.buf + (2 * l) * 18;
            float* b1 = p.buf + (2 * l + 1) * 18;
            #pragma unroll
            for (int j = 0; j < 16; j++) {
                float r0 = p.relT[0][j], r1 = p.relT[1][j], r2 = p.relT[2][j];
                float t0 = fmaf(r2, dw2.x, fmaf(r1, dw1.x, fmaf(r0, dw0.x, db.x)));
                float t1 = fmaf(r2, dw2.y, fmaf(r1, dw1.y, fmaf(r0, dw0.y, db.y)));
                b0[j] = fmaxf(t0, 0.f);
                b1[j] = fmaxf(t1, 0.f);
            }
        }
        __syncwarp();

        // --- pos = t @ d2 + d2b  (register-resident pairs) ---
        ull acc[16];
        {
            float2 bb = *(const float2*)(&s.bias[1][2 * l]);
            wmv(s.w_d2, bb.x, bb.y, p.buf, l, acc);
        }
        float pos0[16], pos1[16];
        #pragma unroll
        for (int pp = 0; pp < 8; pp++) {
            up2(acc[pp],     pos0[2 * pp], pos0[2 * pp + 1]);
            up2(acc[8 + pp], pos1[2 * pp], pos1[2 * pp + 1]);
        }

        // --- gather k rows (register-resident) ---
        float2 kr[16];
        #pragma unroll
        for (int j = 0; j < 16; j++) {
            int nb = p.idx[j];
            kr[j] = *(const float2*)(Kb + ((size_t)(b * NN) + nb) * DM + 2 * l);
        }
        __syncwarp();   // all lanes finished reading t from buf

        // --- h = q - k + pos, channel-major into buf ---
        {
            float* b0 = p.buf + (2 * l) * 18;
            float* b1 = p.buf + (2 * l + 1) * 18;
            #pragma unroll
            for (int j = 0; j < 16; j++) {
                b0[j] = q.x - kr[j].x + pos0[j];
                b1[j] = q.y - kr[j].y + pos1[j];
            }
        }
        __syncwarp();

        // --- u = relu(h @ g1 + g1b) ---
        {
            float2 bb = *(const float2*)(&s.bias[2][2 * l]);
            wmv(s.w_g1, bb.x, bb.y, p.buf, l, acc);
        }
        __syncwarp();   // all lanes finished reading h before overwriting
        {
            float* b0 = p.buf + (2 * l) * 18;
            float* b1 = p.buf + (2 * l + 1) * 18;
            #pragma unroll
            for (int pp = 0; pp < 8; pp++) {
                float u0, u1, u2, u3;
                up2(acc[pp], u0, u1);
                up2(acc[8 + pp], u2, u3);
                *(float2*)(b0 + 2 * pp) = make_float2(fmaxf(u0, 0.f), fmaxf(u1, 0.f));
                *(float2*)(b1 + 2 * pp) = make_float2(fmaxf(u2, 0.f), fmaxf(u3, 0.f));
            }
        }
        __syncwarp();

        // --- logits = u @ g2 + g2b (stay in registers) ---
        {
            float2 bb = *(const float2*)(&s.bias[3][2 * l]);
            wmv(s.w_g2, bb.x, bb.y, p.buf, l, acc);
        }

        // --- gather v rows (latency overlapped with softmax) ---
        float2 vr[16];
        #pragma unroll
        for (int j = 0; j < 16; j++) {
            int nb = p.idx[j];
            vr[j] = *(const float2*)(Vb + ((size_t)(b * NN) + nb) * DM + 2 * l);
        }

        // --- softmax over 16 neighbors, per channel, in registers ---
        float a0[16], a1[16];
        #pragma unroll
        for (int pp = 0; pp < 8; pp++) {
            up2(acc[pp],     a0[2 * pp], a0[2 * pp + 1]);
            up2(acc[8 + pp], a1[2 * pp], a1[2 * pp + 1]);
        }
        float mx0 = a0[0], mx1 = a1[0];
        #pragma unroll
        for (int j = 1; j < 16; j++) { mx0 = fmaxf(mx0, a0[j]); mx1 = fmaxf(mx1, a1[j]); }
        float sm0 = 0.f, sm1 = 0.f;
        #pragma unroll
        for (int j = 0; j < 16; j++) {
            a0[j] = __expf((a0[j] - mx0) * 0.125f); sm0 += a0[j];
            a1[j] = __expf((a1[j] - mx1) * 0.125f); sm1 += a1[j];
        }
        float inv0 = 1.f / sm0, inv1 = 1.f / sm1;

        // --- attn write + weighted sum ---
        float* ao = attn_out + (size_t)m * (KNN * DM) + 2 * l;
        float r0acc = 0.f, r1acc = 0.f;
        #pragma unroll
        for (int j = 0; j < 16; j++) {
            float w0 = a0[j] * inv0, w1 = a1[j] * inv1;
            *(float2*)(ao + (size_t)j * DM) = make_float2(w0, w1);
            r0acc = fmaf(w0, vr[j].x + pos0[j], r0acc);
            r1acc = fmaf(w1, vr[j].y + pos1[j], r1acc);
        }
        *(float2*)(&p.res[2 * l]) = make_float2(r0acc, r1acc);
        __syncwarp();

        // --- out = res @ fc2 + fc2_b + features ---
        {
            ull oacc = *(const ull*)(&s.bias[4][2 * l]);
            #pragma unroll 8
            for (int c = 0; c < 64; c++) {
                float rc = p.res[c];
                ull rp = pk2(rc, rc);
                ull w = *(const ull*)(s.w_fc2 + c * 64 + 2 * l);
                oacc = ffma2(rp, w, oacc);
            }
            float o0, o1; up2(oacc, o0, o1);
            float2 f = *(const float2*)(features + (size_t)m * DM + 2 * l);
            *(float2*)(out + (size_t)m * DM + 2 * l) = make_float2(o0 + f.x, o1 + f.y);
        }
        __syncwarp();   // res/buf WAR guard before next iteration
    }
}

// ================= launch =================
extern "C" void kernel_launch(void* const* d_in, const int* in_sizes, int n_in,
                              void* d_out, int out_size) {
    const float* xyz      = (const float*)d_in[0];
    const float* features = (const float*)d_in[1];
    const int*   knn      = (const int*)d_in[2];
    const float* fc1_w    = (const float*)d_in[3];
    const float* fc1_b    = (const float*)d_in[4];
    const float* fc2_w    = (const float*)d_in[5];
    const float* fc2_b    = (const float*)d_in[6];
    const float* d1_w     = (const float*)d_in[7];
    const float* d1_b     = (const float*)d_in[8];
    const float* d2_w     = (const float*)d_in[9];
    const float* d2_b     = (const float*)d_in[10];
    const float* g1_w     = (const float*)d_in[11];
    const float* g1_b     = (const float*)d_in[12];
    const float* g2_w     = (const float*)d_in[13];
    const float* g2_b     = (const float*)d_in[14];
    const float* wq       = (const float*)d_in[15];
    const float* wk       = (const float*)d_in[16];
    const float* wv       = (const float*)d_in[17];
    float* out = (float*)d_out;

    fold_kernel<<<49, 256>>>(fc1_w, fc1_b, wq, wk, wv);
    qkv_kernel<<<dim3(NPTS / 64, 3), 256>>>(features);

    cudaFuncSetAttribute(main_kernel, cudaFuncAttributeMaxDynamicSharedMemorySize,
                         (int)sizeof(SMem));
    main_kernel<<<296, 256, sizeof(SMem)>>>(xyz, features, knn,
                                            d1_w, d1_b, d2_w, d2_b,
                                            g1_w, g1_b, g2_w, g2_b,
                                            fc2_w, fc2_b, out);
}

// round 6
// speedup vs baseline: 2.2937x; 1.4472x over previous
#include <cuda_runtime.h>
#include <cuda_bf16.h>
#include <stdint.h>
#include <math.h>

#define NB 4
#define NN 8192
#define KNN 16
#define DM 64
#define NPTS (NB * NN)   // 32768

__device__ float g_QKV[3][(size_t)NPTS * DM];
__device__ float g_res[(size_t)NPTS * DM];
__device__ float g_Wf[3][DM * DM];
__device__ float g_bf[3][DM];

// ---------------- bf16 pack helpers ----------------
__device__ __forceinline__ uint32_t pk_lohi(float lo, float hi) {
    uint32_t r;
    asm("cvt.rn.satfinite.bf16x2.f32 %0, %1, %2;" : "=r"(r) : "f"(hi), "f"(lo));
    return r;
}
__device__ __forceinline__ void spack(float x0, float x1, uint32_t& hp, uint32_t& lp) {
    hp = pk_lohi(x0, x1);
    __nv_bfloat162 hb = *reinterpret_cast<__nv_bfloat162*>(&hp);
    lp = pk_lohi(x0 - __bfloat162float(hb.x), x1 - __bfloat162float(hb.y));
}
__device__ __forceinline__ float bf16_part(float x, int tau) {
    float h = __bfloat162float(__float2bfloat16(x));
    return tau ? (x - h) : h;
}

// warp mma: D(16x8) += A(16x16) * B(16x8), bf16 in, fp32 acc
__device__ __forceinline__ void mma_bf16(float c[4], const uint32_t a[4], uint2 b) {
    asm volatile(
        "mma.sync.aligned.m16n8k16.row.col.f32.bf16.bf16.f32 "
        "{%0,%1,%2,%3},{%4,%5,%6,%7},{%8,%9},{%0,%1,%2,%3};"
        : "+f"(c[0]), "+f"(c[1]), "+f"(c[2]), "+f"(c[3])
        : "r"(a[0]), "r"(a[1]), "r"(a[2]), "r"(a[3]), "r"(b.x), "r"(b.y));
}

// ================= Kernel 0: fold fc1 into wq/wk/wv =================
__global__ void fold_kernel(const float* __restrict__ fc1_w, const float* __restrict__ fc1_b,
                            const float* __restrict__ wq, const float* __restrict__ wk,
                            const float* __restrict__ wv) {
    const float* Ws[3] = {wq, wk, wv};
    int t = blockIdx.x * blockDim.x + threadIdx.x;
    int total = 3 * DM * (DM + 1);
    for (int o = t; o < total; o += gridDim.x * blockDim.x) {
        int w = o / (DM * (DM + 1));
        int r = o % (DM * (DM + 1));
        const float* W = Ws[w];
        if (r < DM * DM) {
            int c = r >> 6, f = r & 63;
            float acc = 0.f;
            #pragma unroll 8
            for (int m = 0; m < DM; m++) acc = fmaf(fc1_w[c * DM + m], W[m * DM + f], acc);
            g_Wf[w][c * DM + f] = acc;
        } else {
            int f = r - DM * DM;
            float acc = 0.f;
            #pragma unroll 8
            for (int m = 0; m < DM; m++) acc = fmaf(fc1_b[m], W[m * DM + f], acc);
            g_bf[w][f] = acc;
        }
    }
}

// ================= Kernel 1: Q / XK / XV GEMMs =================
__global__ __launch_bounds__(256) void qkv_kernel(const float* __restrict__ features) {
    __shared__ float in_sh[64][64];
    __shared__ float W_sh[64][64];
    __shared__ float b_sh[64];
    const int w = blockIdx.y;
    const int row0 = blockIdx.x * 64;
    const int tid = threadIdx.x;
    for (int i = tid; i < 4096; i += 256) W_sh[i >> 6][i & 63] = g_Wf[w][i];
    if (tid < 64) b_sh[tid] = g_bf[w][tid];
    {
        const float4* fin = (const float4*)(features + (size_t)row0 * DM);
        float4* in4 = (float4*)&in_sh[0][0];
        for (int i = tid; i < 1024; i += 256) in4[i] = fin[i];
    }
    __syncthreads();
    const int col = tid & 63, rg = tid >> 6;
    float acc[16];
    #pragma unroll
    for (int r = 0; r < 16; r++) acc[r] = b_sh[col];
    #pragma unroll
    for (int c = 0; c < 64; c += 4) {
        float w0 = W_sh[c][col], w1 = W_sh[c + 1][col], w2 = W_sh[c + 2][col], w3 = W_sh[c + 3][col];
        #pragma unroll
        for (int r = 0; r < 16; r++) {
            float4 x = *(const float4*)&in_sh[rg * 16 + r][c];
            float a = acc[r];
            a = fmaf(x.x, w0, a); a = fmaf(x.y, w1, a);
            a = fmaf(x.z, w2, a); a = fmaf(x.w, w3, a);
            acc[r] = a;
        }
    }
    float* outp = g_QKV[w];
    #pragma unroll
    for (int r = 0; r < 16; r++)
        outp[(size_t)(row0 + rg * 16 + r) * DM + col] = acc[r];
}

// ================= Kernel 3: fc2 epilogue =================
__global__ __launch_bounds__(256) void fc2_kernel(const float* __restrict__ fc2w,
                                                  const float* __restrict__ fc2b,
                                                  const float* __restrict__ features,
                                                  float* __restrict__ out) {
    __shared__ float in_sh[64][64];
    __shared__ float W_sh[64][64];
    __shared__ float b_sh[64];
    const int row0 = blockIdx.x * 64;
    const int tid = threadIdx.x;
    for (int i = tid; i < 4096; i += 256) W_sh[i >> 6][i & 63] = fc2w[i];
    if (tid < 64) b_sh[tid] = fc2b[tid];
    {
        const float4* fin = (const float4*)(g_res + (size_t)row0 * DM);
        float4* in4 = (float4*)&in_sh[0][0];
        for (int i = tid; i < 1024; i += 256) in4[i] = fin[i];
    }
    __syncthreads();
    const int col = tid & 63, rg = tid >> 6;
    float acc[16];
    #pragma unroll
    for (int r = 0; r < 16; r++) acc[r] = b_sh[col];
    #pragma unroll
    for (int c = 0; c < 64; c += 4) {
        float w0 = W_sh[c][col], w1 = W_sh[c + 1][col], w2 = W_sh[c + 2][col], w3 = W_sh[c + 3][col];
        #pragma unroll
        for (int r = 0; r < 16; r++) {
            float4 x = *(const float4*)&in_sh[rg * 16 + r][c];
            float a = acc[r];
            a = fmaf(x.x, w0, a); a = fmaf(x.y, w1, a);
            a = fmaf(x.z, w2, a); a = fmaf(x.w, w3, a);
            acc[r] = a;
        }
    }
    #pragma unroll
    for (int r = 0; r < 16; r++) {
        size_t row = (size_t)(row0 + rg * 16 + r);
        out[row * DM + col] = acc[r] + features[row * DM + col];
    }
}

// ================= Kernel 2: mma.sync fused transformer =================
// B fragments: bf[stage*2+term][kblock j][ntile t][lane] = uint2
//   reg.x = {W[k0][n], W[k0+1][n]}, reg.y = {W[k0+8][n], W[k0+9][n]}
//   k0 = 16j + (lane%4)*2, n = 8t + lane/4
struct SMemM {
    uint2 bf[6][4][8][32];   // 48 KB
    float d1[192];
    float bD1[64], bD2[64], bG1[64], bG2[64];
};

__device__ __forceinline__ void run_stage(float acc[8][4],
                                          const uint32_t ah[4][4], const uint32_t al[4][4],
                                          const uint2 (*__restrict__ BH)[8][32],
                                          const uint2 (*__restrict__ BL)[8][32], int lane) {
    #pragma unroll
    for (int j = 0; j < 4; j++)
        #pragma unroll
        for (int t = 0; t < 8; t++) mma_bf16(acc[t], ah[j], BH[j][t][lane]);
    #pragma unroll
    for (int j = 0; j < 4; j++)
        #pragma unroll
        for (int t = 0; t < 8; t++) mma_bf16(acc[t], al[j], BH[j][t][lane]);
    #pragma unroll
    for (int j = 0; j < 4; j++)
        #pragma unroll
        for (int t = 0; t < 8; t++) mma_bf16(acc[t], ah[j], BL[j][t][lane]);
}

__global__ __launch_bounds__(256, 2) void main_kernel(
    const float* __restrict__ xyz, const int* __restrict__ knn,
    const float* __restrict__ d1w, const float* __restrict__ d1b,
    const float* __restrict__ d2w, const float* __restrict__ d2b,
    const float* __restrict__ g1w, const float* __restrict__ g1b,
    const float* __restrict__ g2w, const float* __restrict__ g2b,
    float* __restrict__ out) {
    extern __shared__ __align__(16) unsigned char smraw[];
    SMemM* S = reinterpret_cast<SMemM*>(smraw);
    const int tid = threadIdx.x;

    // build B fragments (once per CTA)
    {
        const float* wsrc[3] = {d2w, g1w, g2w};
        for (int e = tid; e < 6 * 4 * 8 * 32; e += 256) {
            int ln = e & 31, t = (e >> 5) & 7, j = (e >> 8) & 3, st = e >> 10;
            int s = st >> 1, tau = st & 1;
            const float* W = wsrc[s];
            int k0 = 16 * j + (ln & 3) * 2;
            int n = 8 * t + (ln >> 2);
            float w00 = W[k0 * 64 + n], w01 = W[(k0 + 1) * 64 + n];
            float w10 = W[(k0 + 8) * 64 + n], w11 = W[(k0 + 9) * 64 + n];
            uint2 r;
            r.x = pk_lohi(bf16_part(w00, tau), bf16_part(w01, tau));
            r.y = pk_lohi(bf16_part(w10, tau), bf16_part(w11, tau));
            S->bf[st][j][t][ln] = r;
        }
    }
    for (int i = tid; i < 192; i += 256) S->d1[i] = d1w[i];
    if (tid < 64) {
        S->bD1[tid] = d1b[tid]; S->bD2[tid] = d2b[tid];
        S->bG1[tid] = g1b[tid]; S->bG2[tid] = g2b[tid];
    }
    __syncthreads();

    const int wid = tid >> 5, lane = tid & 31;
    const int r0 = lane >> 2, r1 = r0 + 8;   // this thread's 2 neighbor rows
    const int cq = (lane & 3) * 2;           // col offset within 8-wide n tile
    float* __restrict__ attn_out = out + (size_t)NPTS * DM;

    for (int m = blockIdx.x * 8 + wid; m < NPTS; m += gridDim.x * 8) {
        const int base = (m >> 13) * NN;
        const int i0 = knn[m * KNN + r0];
        const int i1 = knn[m * KNN + r1];
        const float* __restrict__ Kr0 = g_QKV[1] + (size_t)(base + i0) * DM;
        const float* __restrict__ Kr1 = g_QKV[1] + (size_t)(base + i1) * DM;
        const float* __restrict__ Vr0 = g_QKV[2] + (size_t)(base + i0) * DM;
        const float* __restrict__ Vr1 = g_QKV[2] + (size_t)(base + i1) * DM;
        const float cx = xyz[3 * m], cy = xyz[3 * m + 1], cz = xyz[3 * m + 2];
        const float* x0p = xyz + (size_t)(base + i0) * 3;
        const float* x1p = xyz + (size_t)(base + i1) * 3;
        const float rx0 = cx - x0p[0], ry0 = cy - x0p[1], rz0 = cz - x0p[2];
        const float rx1 = cx - x1p[0], ry1 = cy - x1p[1], rz1 = cz - x1p[2];

        uint32_t ah[4][4], al[4][4];
        // ---- stage 1 A: t = relu(rel @ d1 + d1b), built directly in frag layout ----
        #pragma unroll
        for (int j = 0; j < 4; j++) {
            #pragma unroll
            for (int half = 0; half < 2; half++) {
                int c = 16 * j + 8 * half + cq;
                float b0 = S->bD1[c], b1 = S->bD1[c + 1];
                float wx0 = S->d1[c], wy0 = S->d1[64 + c], wz0 = S->d1[128 + c];
                float wx1 = S->d1[c + 1], wy1 = S->d1[65 + c], wz1 = S->d1[129 + c];
                float t00 = fmaxf(fmaf(rz0, wz0, fmaf(ry0, wy0, fmaf(rx0, wx0, b0))), 0.f);
                float t01 = fmaxf(fmaf(rz0, wz1, fmaf(ry0, wy1, fmaf(rx0, wx1, b1))), 0.f);
                float t10 = fmaxf(fmaf(rz1, wz0, fmaf(ry1, wy0, fmaf(rx1, wx0, b0))), 0.f);
                float t11 = fmaxf(fmaf(rz1, wz1, fmaf(ry1, wy1, fmaf(rx1, wx1, b1))), 0.f);
                spack(t00, t01, ah[j][2 * half], al[j][2 * half]);
                spack(t10, t11, ah[j][2 * half + 1], al[j][2 * half + 1]);
            }
        }

        float acc[8][4];
        #pragma unroll
        for (int t = 0; t < 8; t++) { acc[t][0] = acc[t][1] = acc[t][2] = acc[t][3] = 0.f; }
        run_stage(acc, ah, al, S->bf[0], S->bf[1], lane);

        // ---- pos = D + d2b (kept in frag layout) ----
        float pos[8][4];
        #pragma unroll
        for (int t = 0; t < 8; t++) {
            int c = 8 * t + cq;
            float b0 = S->bD2[c], b1 = S->bD2[c + 1];
            pos[t][0] = acc[t][0] + b0; pos[t][1] = acc[t][1] + b1;
            pos[t][2] = acc[t][2] + b0; pos[t][3] = acc[t][3] + b1;
        }

        // ---- h = q - k + pos -> next A frags ----
        {
            const float* Qrow = g_QKV[0] + (size_t)m * DM;
            #pragma unroll
            for (int j = 0; j < 4; j++) {
                #pragma unroll
                for (int half = 0; half < 2; half++) {
                    int t = 2 * j + half;
                    int c = 8 * t + cq;
                    float2 q2 = *(const float2*)(Qrow + c);
                    float2 k0 = *(const float2*)(Kr0 + c);
                    float2 k1 = *(const float2*)(Kr1 + c);
                    float h00 = q2.x - k0.x + pos[t][0];
                    float h01 = q2.y - k0.y + pos[t][1];
                    float h10 = q2.x - k1.x + pos[t][2];
                    float h11 = q2.y - k1.y + pos[t][3];
                    spack(h00, h01, ah[j][2 * half], al[j][2 * half]);
                    spack(h10, h11, ah[j][2 * half + 1], al[j][2 * half + 1]);
                }
            }
        }
        #pragma unroll
        for (int t = 0; t < 8; t++) { acc[t][0] = acc[t][1] = acc[t][2] = acc[t][3] = 0.f; }
        run_stage(acc, ah, al, S->bf[2], S->bf[3], lane);

        // ---- u = relu(D + g1b) -> next A frags ----
        #pragma unroll
        for (int j = 0; j < 4; j++) {
            #pragma unroll
            for (int half = 0; half < 2; half++) {
                int t = 2 * j + half;
                int c = 8 * t + cq;
                float b0 = S->bG1[c], b1 = S->bG1[c + 1];
                float u00 = fmaxf(acc[t][0] + b0, 0.f), u01 = fmaxf(acc[t][1] + b1, 0.f);
                float u10 = fmaxf(acc[t][2] + b0, 0.f), u11 = fmaxf(acc[t][3] + b1, 0.f);
                spack(u00, u01, ah[j][2 * half], al[j][2 * half]);
                spack(u10, u11, ah[j][2 * half + 1], al[j][2 * half + 1]);
            }
        }
        // prefetch v rows before the last MMA stage to hide gather latency
        float2 v0pre[8], v1pre[8];
        #pragma unroll
        for (int t = 0; t < 8; t++) {
            int c = 8 * t + cq;
            v0pre[t] = *(const float2*)(Vr0 + c);
            v1pre[t] = *(const float2*)(Vr1 + c);
        }
        #pragma unroll
        for (int t = 0; t < 8; t++) { acc[t][0] = acc[t][1] = acc[t][2] = acc[t][3] = 0.f; }
        run_stage(acc, ah, al, S->bf[4], S->bf[5], lane);

        // ---- softmax over 16 neighbors (rows) per channel + outputs ----
        {
            float* ao = attn_out + (size_t)m * (KNN * DM);
            float* ro = g_res + (size_t)m * DM;
            #pragma unroll
            for (int t = 0; t < 8; t++) {
                int c = 8 * t + cq;
                float b0 = S->bG2[c], b1 = S->bG2[c + 1];
                float l00 = acc[t][0] + b0, l01 = acc[t][1] + b1;
                float l10 = acc[t][2] + b0, l11 = acc[t][3] + b1;
                float m0 = fmaxf(l00, l10), m1 = fmaxf(l01, l11);
                #pragma unroll
                for (int o = 4; o < 32; o <<= 1) {
                    m0 = fmaxf(m0, __shfl_xor_sync(0xffffffffu, m0, o));
                    m1 = fmaxf(m1, __shfl_xor_sync(0xffffffffu, m1, o));
                }
                float e00 = __expf((l00 - m0) * 0.125f), e10 = __expf((l10 - m0) * 0.125f);
                float e01 = __expf((l01 - m1) * 0.125f), e11 = __expf((l11 - m1) * 0.125f);
                float s0 = e00 + e10, s1 = e01 + e11;
                #pragma unroll
                for (int o = 4; o < 32; o <<= 1) {
                    s0 += __shfl_xor_sync(0xffffffffu, s0, o);
                    s1 += __shfl_xor_sync(0xffffffffu, s1, o);
                }
                float inv0 = 1.f / s0, inv1 = 1.f / s1;
                float a00 = e00 * inv0, a01 = e01 * inv1;
                float a10 = e10 * inv0, a11 = e11 * inv1;
                *(float2*)(ao + r0 * DM + c) = make_float2(a00, a01);
                *(float2*)(ao + r1 * DM + c) = make_float2(a10, a11);
                float rc0 = a00 * (v0pre[t].x + pos[t][0]) + a10 * (v1pre[t].x + pos[t][2]);
                float rc1 = a01 * (v0pre[t].y + pos[t][1]) + a11 * (v1pre[t].y + pos[t][3]);
                #pragma unroll
                for (int o = 4; o < 32; o <<= 1) {
                    rc0 += __shfl_xor_sync(0xffffffffu, rc0, o);
                    rc1 += __shfl_xor_sync(0xffffffffu, rc1, o);
                }
                if (lane < 4) *(float2*)(ro + c) = make_float2(rc0, rc1);
            }
        }
    }
}

// ================= launch =================
extern "C" void kernel_launch(void* const* d_in, const int* in_sizes, int n_in,
                              void* d_out, int out_size) {
    const float* xyz      = (const float*)d_in[0];
    const float* features = (const float*)d_in[1];
    const int*   knn      = (const int*)d_in[2];
    const float* fc1_w    = (const float*)d_in[3];
    const float* fc1_b    = (const float*)d_in[4];
    const float* fc2_w    = (const float*)d_in[5];
    const float* fc2_b    = (const float*)d_in[6];
    const float* d1_w     = (const float*)d_in[7];
    const float* d1_b     = (const float*)d_in[8];
    const float* d2_w     = (const float*)d_in[9];
    const float* d2_b     = (const float*)d_in[10];
    const float* g1_w     = (const float*)d_in[11];
    const float* g1_b     = (const float*)d_in[12];
    const float* g2_w     = (const float*)d_in[13];
    const float* g2_b     = (const float*)d_in[14];
    const float* wq       = (const float*)d_in[15];
    const float* wk       = (const float*)d_in[16];
    const float* wv       = (const float*)d_in[17];
    float* out = (float*)d_out;

    fold_kernel<<<49, 256>>>(fc1_w, fc1_b, wq, wk, wv);
    qkv_kernel<<<dim3(NPTS / 64, 3), 256>>>(features);

    cudaFuncSetAttribute(main_kernel, cudaFuncAttributeMaxDynamicSharedMemorySize,
                         (int)sizeof(SMemM));
    main_kernel<<<296, 256, sizeof(SMemM)>>>(xyz, knn,
                                             d1_w, d1_b, d2_w, d2_b,
                                             g1_w, g1_b, g2_w, g2_b, out);

    fc2_kernel<<<NPTS / 64, 256>>>(fc2_w, fc2_b, features, out);
}

// round 8
// speedup vs baseline: 2.7450x; 1.1968x over previous
#include <cuda_runtime.h>
#include <cuda_bf16.h>
#include <stdint.h>
#include <math.h>

#define NB 4
#define NN 8192
#define KNN 16
#define DM 64
#define NPTS (NB * NN)   // 32768

__device__ float g_QKV[3][(size_t)NPTS * DM];
__device__ float g_res[(size_t)NPTS * DM];
__device__ float g_bf[3][DM];
// frag store: [mat 0..6][term hi/lo][1024]  (mat: 0-2 folded fc1@{wq,wk,wv}, 3 d2, 4 g1, 5 g2, 6 fc2)
__device__ uint2 g_frag[7][2][1024];

// ---------------- bf16 helpers ----------------
__device__ __forceinline__ uint32_t pk_lohi(float lo, float hi) {
    uint32_t r;
    asm("cvt.rn.satfinite.bf16x2.f32 %0, %1, %2;" : "=r"(r) : "f"(hi), "f"(lo));
    return r;
}
__device__ __forceinline__ void spack(float x0, float x1, uint32_t& hp, uint32_t& lp) {
    hp = pk_lohi(x0, x1);
    __nv_bfloat162 hb = *reinterpret_cast<__nv_bfloat162*>(&hp);
    lp = pk_lohi(x0 - __bfloat162float(hb.x), x1 - __bfloat162float(hb.y));
}
__device__ __forceinline__ float bf16_part(float x, int tau) {
    float h = __bfloat162float(__float2bfloat16(x));
    return tau ? (x - h) : h;
}
__device__ __forceinline__ void mma_bf16(float c[4], const uint32_t a[4], uint2 b) {
    asm volatile(
        "mma.sync.aligned.m16n8k16.row.col.f32.bf16.bf16.f32 "
        "{%0,%1,%2,%3},{%4,%5,%6,%7},{%8,%9},{%0,%1,%2,%3};"
        : "+f"(c[0]), "+f"(c[1]), "+f"(c[2]), "+f"(c[3])
        : "r"(a[0]), "r"(a[1]), "r"(a[2]), "r"(a[3]), "r"(b.x), "r"(b.y));
}

// 3-term stage: acc += A(16x64) * B(64x64) with hi/lo split
__device__ __forceinline__ void run_stage(float acc[8][4],
                                          const uint32_t ah[4][4], const uint32_t al[4][4],
                                          const uint2* __restrict__ BH,
                                          const uint2* __restrict__ BL, int lane) {
    #pragma unroll
    for (int j = 0; j < 4; j++)
        #pragma unroll
        for (int t = 0; t < 8; t++) mma_bf16(acc[t], ah[j], BH[(j * 8 + t) * 32 + lane]);
    #pragma unroll
    for (int j = 0; j < 4; j++)
        #pragma unroll
        for (int t = 0; t < 8; t++) mma_bf16(acc[t], al[j], BH[(j * 8 + t) * 32 + lane]);
    #pragma unroll
    for (int j = 0; j < 4; j++)
        #pragma unroll
        for (int t = 0; t < 8; t++) mma_bf16(acc[t], ah[j], BL[(j * 8 + t) * 32 + lane]);
}

// ================= prep: fold + all B fragments =================
__global__ void prep_kernel(const float* __restrict__ fc1_w, const float* __restrict__ fc1_b,
                            const float* __restrict__ wq, const float* __restrict__ wk,
                            const float* __restrict__ wv,
                            const float* __restrict__ d2w, const float* __restrict__ g1w,
                            const float* __restrict__ g2w, const float* __restrict__ fc2w) {
    int e = blockIdx.x * 256 + threadIdx.x;
    if (e < 7 * 2048) {
        int mat = e >> 11, term = (e >> 10) & 1, r = e & 1023;
        int j = r >> 8, t = (r >> 5) & 7, ln = r & 31;
        int k0 = 16 * j + (ln & 3) * 2, n = 8 * t + (ln >> 2);
        float w00, w01, w10, w11;
        if (mat < 3) {
            const float* Wsel = (mat == 0) ? wq : ((mat == 1) ? wk : wv);
            float a0 = 0.f, a1 = 0.f, a2 = 0.f, a3 = 0.f;
            #pragma unroll 8
            for (int m = 0; m < 64; m++) {
                float wm = Wsel[m * 64 + n];
                a0 = fmaf(fc1_w[k0 * 64 + m], wm, a0);
                a1 = fmaf(fc1_w[(k0 + 1) * 64 + m], wm, a1);
                a2 = fmaf(fc1_w[(k0 + 8) * 64 + m], wm, a2);
                a3 = fmaf(fc1_w[(k0 + 9) * 64 + m], wm, a3);
            }
            w00 = a0; w01 = a1; w10 = a2; w11 = a3;
        } else {
            const float* W = (mat == 3) ? d2w : ((mat == 4) ? g1w : ((mat == 5) ? g2w : fc2w));
            w00 = W[k0 * 64 + n]; w01 = W[(k0 + 1) * 64 + n];
            w10 = W[(k0 + 8) * 64 + n]; w11 = W[(k0 + 9) * 64 + n];
        }
        uint2 rr;
        rr.x = pk_lohi(bf16_part(w00, term), bf16_part(w01, term));
        rr.y = pk_lohi(bf16_part(w10, term), bf16_part(w11, term));
        g_frag[mat][term][r] = rr;
    } else if (e < 7 * 2048 + 192) {
        int o = e - 7 * 2048, w = o >> 6, f = o & 63;
        const float* Wsel = (w == 0) ? wq : ((w == 1) ? wk : wv);
        float acc = 0.f;
        #pragma unroll 8
        for (int m = 0; m < 64; m++) acc = fmaf(fc1_b[m], Wsel[m * 64 + f], acc);
        g_bf[w][f] = acc;
    }
}

// ================= qkv3: Q/XK/XV via mma =================
struct SQ { uint2 bf[6][1024]; float bias[3][64]; };

__global__ __launch_bounds__(256, 2) void qkv3_kernel(const float* __restrict__ features) {
    extern __shared__ __align__(16) unsigned char smraw[];
    SQ* S = reinterpret_cast<SQ*>(smraw);
    const int tid = threadIdx.x;
    {
        const uint4* src = (const uint4*)&g_frag[0][0][0];
        uint4* dst = (uint4*)&S->bf[0][0];
        for (int i = tid; i < 3072; i += 256) dst[i] = src[i];   // 6*1024 uint2 = 3072 uint4
        for (int i = tid; i < 192; i += 256) S->bias[i >> 6][i & 63] = g_bf[i >> 6][i & 63];
    }
    __syncthreads();

    const int wid = tid >> 5, lane = tid & 31;
    const int r0 = lane >> 2, r1 = r0 + 8, cq = (lane & 3) * 2;
    const int m0 = blockIdx.x * 128 + wid * 16;

    uint32_t ah[4][4], al[4][4];
    const float* A0 = features + (size_t)(m0 + r0) * DM;
    const float* A1 = features + (size_t)(m0 + r1) * DM;
    #pragma unroll
    for (int j = 0; j < 4; j++) {
        int c = 16 * j + cq;
        float2 x00 = *(const float2*)(A0 + c);
        float2 x10 = *(const float2*)(A1 + c);
        float2 x01 = *(const float2*)(A0 + c + 8);
        float2 x11 = *(const float2*)(A1 + c + 8);
        spack(x00.x, x00.y, ah[j][0], al[j][0]);
        spack(x10.x, x10.y, ah[j][1], al[j][1]);
        spack(x01.x, x01.y, ah[j][2], al[j][2]);
        spack(x11.x, x11.y, ah[j][3], al[j][3]);
    }

    #pragma unroll
    for (int w = 0; w < 3; w++) {
        float acc[8][4];
        #pragma unroll
        for (int t = 0; t < 8; t++) { acc[t][0] = acc[t][1] = acc[t][2] = acc[t][3] = 0.f; }
        run_stage(acc, ah, al, &S->bf[2 * w][0], &S->bf[2 * w + 1][0], lane);
        float* O = g_QKV[w];
        #pragma unroll
        for (int t = 0; t < 8; t++) {
            int c = 8 * t + cq;
            float b0 = S->bias[w][c], b1 = S->bias[w][c + 1];
            *(float2*)(O + (size_t)(m0 + r0) * DM + c) = make_float2(acc[t][0] + b0, acc[t][1] + b1);
            *(float2*)(O + (size_t)(m0 + r1) * DM + c) = make_float2(acc[t][2] + b0, acc[t][3] + b1);
        }
    }
}

// ================= fc2 via mma =================
struct SF { uint2 bf[2][1024]; float bias[64]; };

__global__ __launch_bounds__(256, 2) void fc2_kernel(const float* __restrict__ fc2b,
                                                     const float* __restrict__ features,
                                                     float* __restrict__ out) {
    extern __shared__ __align__(16) unsigned char smraw[];
    SF* S = reinterpret_cast<SF*>(smraw);
    const int tid = threadIdx.x;
    {
        const uint4* src = (const uint4*)&g_frag[6][0][0];
        uint4* dst = (uint4*)&S->bf[0][0];
        for (int i = tid; i < 1024; i += 256) dst[i] = src[i];   // 2*1024 uint2 = 1024 uint4
        if (tid < 64) S->bias[tid] = fc2b[tid];
    }
    __syncthreads();

    const int wid = tid >> 5, lane = tid & 31;
    const int r0 = lane >> 2, r1 = r0 + 8, cq = (lane & 3) * 2;
    const int m0 = blockIdx.x * 128 + wid * 16;

    uint32_t ah[4][4], al[4][4];
    const float* A0 = g_res + (size_t)(m0 + r0) * DM;
    const float* A1 = g_res + (size_t)(m0 + r1) * DM;
    #pragma unroll
    for (int j = 0; j < 4; j++) {
        int c = 16 * j + cq;
        float2 x00 = *(const float2*)(A0 + c);
        float2 x10 = *(const float2*)(A1 + c);
        float2 x01 = *(const float2*)(A0 + c + 8);
        float2 x11 = *(const float2*)(A1 + c + 8);
        spack(x00.x, x00.y, ah[j][0], al[j][0]);
        spack(x10.x, x10.y, ah[j][1], al[j][1]);
        spack(x01.x, x01.y, ah[j][2], al[j][2]);
        spack(x11.x, x11.y, ah[j][3], al[j][3]);
    }
    float acc[8][4];
    #pragma unroll
    for (int t = 0; t < 8; t++) { acc[t][0] = acc[t][1] = acc[t][2] = acc[t][3] = 0.f; }
    run_stage(acc, ah, al, &S->bf[0][0], &S->bf[1][0], lane);
    #pragma unroll
    for (int t = 0; t < 8; t++) {
        int c = 8 * t + cq;
        float b0 = S->bias[c], b1 = S->bias[c + 1];
        float2 f0 = *(const float2*)(features + (size_t)(m0 + r0) * DM + c);
        float2 f1 = *(const float2*)(features + (size_t)(m0 + r1) * DM + c);
        *(float2*)(out + (size_t)(m0 + r0) * DM + c) = make_float2(acc[t][0] + b0 + f0.x, acc[t][1] + b1 + f0.y);
        *(float2*)(out + (size_t)(m0 + r1) * DM + c) = make_float2(acc[t][2] + b0 + f1.x, acc[t][3] + b1 + f1.y);
    }
}

// ================= main: fused per-neighbor transformer =================
struct SMemM {
    uint2 bf[6][1024];   // d2 hi/lo, g1 hi/lo, g2 hi/lo
    float d1[192];
    float bD1[64], bD2[64], bG1[64], bG2[64];
};

__global__ __launch_bounds__(256, 2) void main_kernel(
    const float* __restrict__ xyz, const int* __restrict__ knn,
    const float* __restrict__ d1w, const float* __restrict__ d1b,
    const float* __restrict__ d2b, const float* __restrict__ g1b,
    const float* __restrict__ g2b, float* __restrict__ out) {
    extern __shared__ __align__(16) unsigned char smraw[];
    SMemM* S = reinterpret_cast<SMemM*>(smraw);
    const int tid = threadIdx.x;
    {
        const uint4* src = (const uint4*)&g_frag[3][0][0];
        uint4* dst = (uint4*)&S->bf[0][0];
        for (int i = tid; i < 3072; i += 256) dst[i] = src[i];   // 6*1024 uint2 = 3072 uint4
    }
    for (int i = tid; i < 192; i += 256) S->d1[i] = d1w[i];
    if (tid < 64) {
        S->bD1[tid] = d1b[tid]; S->bD2[tid] = d2b[tid];
        S->bG1[tid] = g1b[tid]; S->bG2[tid] = g2b[tid];
    }
    __syncthreads();

    const int wid = tid >> 5, lane = tid & 31;
    const int r0 = lane >> 2, r1 = r0 + 8;
    const int cq = (lane & 3) * 2;
    float* __restrict__ attn_out = out + (size_t)NPTS * DM;

    for (int m = blockIdx.x * 8 + wid; m < NPTS; m += gridDim.x * 8) {
        const int base = (m >> 13) * NN;
        const int i0 = knn[m * KNN + r0];
        const int i1 = knn[m * KNN + r1];
        const float cx = xyz[3 * m], cy = xyz[3 * m + 1], cz = xyz[3 * m + 2];
        const float* x0p = xyz + (size_t)(base + i0) * 3;
        const float* x1p = xyz + (size_t)(base + i1) * 3;
        const float rx0 = cx - x0p[0], ry0 = cy - x0p[1], rz0 = cz - x0p[2];
        const float rx1 = cx - x1p[0], ry1 = cy - x1p[1], rz1 = cz - x1p[2];

        uint32_t ah[4][4], al[4][4];
        // ---- t = relu(rel @ d1 + d1b) in frag layout ----
        #pragma unroll
        for (int j = 0; j < 4; j++) {
            #pragma unroll
            for (int half = 0; half < 2; half++) {
                int c = 16 * j + 8 * half + cq;
                float b0 = S->bD1[c], b1 = S->bD1[c + 1];
                float wx0 = S->d1[c], wy0 = S->d1[64 + c], wz0 = S->d1[128 + c];
                float wx1 = S->d1[c + 1], wy1 = S->d1[65 + c], wz1 = S->d1[129 + c];
                float t00 = fmaxf(fmaf(rz0, wz0, fmaf(ry0, wy0, fmaf(rx0, wx0, b0))), 0.f);
                float t01 = fmaxf(fmaf(rz0, wz1, fmaf(ry0, wy1, fmaf(rx0, wx1, b1))), 0.f);
                float t10 = fmaxf(fmaf(rz1, wz0, fmaf(ry1, wy0, fmaf(rx1, wx0, b0))), 0.f);
                float t11 = fmaxf(fmaf(rz1, wz1, fmaf(ry1, wy1, fmaf(rx1, wx1, b1))), 0.f);
                spack(t00, t01, ah[j][2 * half], al[j][2 * half]);
                spack(t10, t11, ah[j][2 * half + 1], al[j][2 * half + 1]);
            }
        }
        float acc[8][4];
        #pragma unroll
        for (int t = 0; t < 8; t++) { acc[t][0] = acc[t][1] = acc[t][2] = acc[t][3] = 0.f; }
        run_stage(acc, ah, al, &S->bf[0][0], &S->bf[1][0], lane);

        // ---- pos = D + d2b ----
        float pos[8][4];
        #pragma unroll
        for (int t = 0; t < 8; t++) {
            int c = 8 * t + cq;
            float b0 = S->bD2[c], b1 = S->bD2[c + 1];
            pos[t][0] = acc[t][0] + b0; pos[t][1] = acc[t][1] + b1;
            pos[t][2] = acc[t][2] + b0; pos[t][3] = acc[t][3] + b1;
        }

        // ---- h = q - k + pos ----
        {
            const float* Qrow = g_QKV[0] + (size_t)m * DM;
            const float* Kr0 = g_QKV[1] + (size_t)(base + i0) * DM;
            const float* Kr1 = g_QKV[1] + (size_t)(base + i1) * DM;
            #pragma unroll
            for (int j = 0; j < 4; j++) {
                #pragma unroll
                for (int half = 0; half < 2; half++) {
                    int t = 2 * j + half;
                    int c = 8 * t + cq;
                    float2 q2 = *(const float2*)(Qrow + c);
                    float2 k0 = *(const float2*)(Kr0 + c);
                    float2 k1 = *(const float2*)(Kr1 + c);
                    float h00 = q2.x - k0.x + pos[t][0];
                    float h01 = q2.y - k0.y + pos[t][1];
                    float h10 = q2.x - k1.x + pos[t][2];
                    float h11 = q2.y - k1.y + pos[t][3];
                    spack(h00, h01, ah[j][2 * half], al[j][2 * half]);
                    spack(h10, h11, ah[j][2 * half + 1], al[j][2 * half + 1]);
                }
            }
        }
        #pragma unroll
        for (int t = 0; t < 8; t++) { acc[t][0] = acc[t][1] = acc[t][2] = acc[t][3] = 0.f; }
        run_stage(acc, ah, al, &S->bf[2][0], &S->bf[3][0], lane);

        // ---- u = relu(D + g1b) ----
        #pragma unroll
        for (int j = 0; j < 4; j++) {
            #pragma unroll
            for (int half = 0; half < 2; half++) {
                int t = 2 * j + half;
                int c = 8 * t + cq;
                float b0 = S->bG1[c], b1 = S->bG1[c + 1];
                float u00 = fmaxf(acc[t][0] + b0, 0.f), u01 = fmaxf(acc[t][1] + b1, 0.f);
                float u10 = fmaxf(acc[t][2] + b0, 0.f), u11 = fmaxf(acc[t][3] + b1, 0.f);
                spack(u00, u01, ah[j][2 * half], al[j][2 * half]);
                spack(u10, u11, ah[j][2 * half + 1], al[j][2 * half + 1]);
            }
        }
        #pragma unroll
        for (int t = 0; t < 8; t++) { acc[t][0] = acc[t][1] = acc[t][2] = acc[t][3] = 0.f; }
        run_stage(acc, ah, al, &S->bf[4][0], &S->bf[5][0], lane);

        // ---- softmax over neighbors + outputs (V loaded here) ----
        {
            const float* Vr0 = g_QKV[2] + (size_t)(base + i0) * DM;
            const float* Vr1 = g_QKV[2] + (size_t)(base + i1) * DM;
            float* ao = attn_out + (size_t)m * (KNN * DM);
            float* ro = g_res + (size_t)m * DM;
            #pragma unroll
            for (int t = 0; t < 8; t++) {
                int c = 8 * t + cq;
                float b0 = S->bG2[c], b1 = S->bG2[c + 1];
                float l00 = acc[t][0] + b0, l01 = acc[t][1] + b1;
                float l10 = acc[t][2] + b0, l11 = acc[t][3] + b1;
                float m0 = fmaxf(l00, l10), m1 = fmaxf(l01, l11);
                #pragma unroll
                for (int o = 4; o < 32; o <<= 1) {
                    m0 = fmaxf(m0, __shfl_xor_sync(0xffffffffu, m0, o));
                    m1 = fmaxf(m1, __shfl_xor_sync(0xffffffffu, m1, o));
                }
                float e00 = __expf((l00 - m0) * 0.125f), e10 = __expf((l10 - m0) * 0.125f);
                float e01 = __expf((l01 - m1) * 0.125f), e11 = __expf((l11 - m1) * 0.125f);
                float s0 = e00 + e10, s1 = e01 + e11;
                #pragma unroll
                for (int o = 4; o < 32; o <<= 1) {
                    s0 += __shfl_xor_sync(0xffffffffu, s0, o);
                    s1 += __shfl_xor_sync(0xffffffffu, s1, o);
                }
                float inv0 = 1.f / s0, inv1 = 1.f / s1;
                float a00 = e00 * inv0, a01 = e01 * inv1;
                float a10 = e10 * inv0, a11 = e11 * inv1;
                *(float2*)(ao + r0 * DM + c) = make_float2(a00, a01);
                *(float2*)(ao + r1 * DM + c) = make_float2(a10, a11);
                float2 v0 = *(const float2*)(Vr0 + c);
                float2 v1 = *(const float2*)(Vr1 + c);
                float rc0 = a00 * (v0.x + pos[t][0]) + a10 * (v1.x + pos[t][2]);
                float rc1 = a01 * (v0.y + pos[t][1]) + a11 * (v1.y + pos[t][3]);
                #pragma unroll
                for (int o = 4; o < 32; o <<= 1) {
                    rc0 += __shfl_xor_sync(0xffffffffu, rc0, o);
                    rc1 += __shfl_xor_sync(0xffffffffu, rc1, o);
                }
                if (lane < 4) *(float2*)(ro + c) = make_float2(rc0, rc1);
            }
        }
    }
}

// ================= launch =================
extern "C" void kernel_launch(void* const* d_in, const int* in_sizes, int n_in,
                              void* d_out, int out_size) {
    const float* xyz      = (const float*)d_in[0];
    const float* features = (const float*)d_in[1];
    const int*   knn      = (const int*)d_in[2];
    const float* fc1_w    = (const float*)d_in[3];
    const float* fc1_b    = (const float*)d_in[4];
    const float* fc2_w    = (const float*)d_in[5];
    const float* fc2_b    = (const float*)d_in[6];
    const float* d1_w     = (const float*)d_in[7];
    const float* d1_b     = (const float*)d_in[8];
    const float* d2_w     = (const float*)d_in[9];
    const float* d2_b     = (const float*)d_in[10];
    const float* g1_w     = (const float*)d_in[11];
    const float* g1_b     = (const float*)d_in[12];
    const float* g2_w     = (const float*)d_in[13];
    const float* g2_b     = (const float*)d_in[14];
    const float* wq       = (const float*)d_in[15];
    const float* wk       = (const float*)d_in[16];
    const float* wv       = (const float*)d_in[17];
    float* out = (float*)d_out;

    prep_kernel<<<57, 256>>>(fc1_w, fc1_b, wq, wk, wv, d2_w, g1_w, g2_w, fc2_w);

    cudaFuncSetAttribute(qkv3_kernel, cudaFuncAttributeMaxDynamicSharedMemorySize, (int)sizeof(SQ));
    qkv3_kernel<<<NPTS / 128, 256, sizeof(SQ)>>>(features);

    cudaFuncSetAttribute(main_kernel, cudaFuncAttributeMaxDynamicSharedMemorySize, (int)sizeof(SMemM));
    main_kernel<<<296, 256, sizeof(SMemM)>>>(xyz, knn, d1_w, d1_b, d2_b, g1_b, g2_b, out);

    cudaFuncSetAttribute(fc2_kernel, cudaFuncAttributeMaxDynamicSharedMemorySize, (int)sizeof(SF));
    fc2_kernel<<<NPTS / 128, 256, sizeof(SF)>>>(fc2_b, features, out);
}

// round 9
// speedup vs baseline: 2.9380x; 1.0703x over previous
#include <cuda_runtime.h>
#include <cuda_bf16.h>
#include <stdint.h>
#include <math.h>

#define NB 4
#define NN 8192
#define KNN 16
#define DM 64
#define NPTS (NB * NN)   // 32768

__device__ float g_QKV[3][(size_t)NPTS * DM];
__device__ float g_res[(size_t)NPTS * DM];
__device__ float g_bf[3][DM];
// frag store: [mat 0..6][1024] uint4 = {bh.x, bh.y, bl.x, bl.y}
// (mat: 0-2 folded fc1@{wq,wk,wv}, 3 d2, 4 g1, 5 g2, 6 fc2)
__device__ uint4 g_frag[7][1024];

// ---------------- bf16 helpers ----------------
__device__ __forceinline__ uint32_t pk_lohi(float lo, float hi) {
    uint32_t r;
    asm("cvt.rn.satfinite.bf16x2.f32 %0, %1, %2;" : "=r"(r) : "f"(hi), "f"(lo));
    return r;
}
__device__ __forceinline__ void spack(float x0, float x1, uint32_t& hp, uint32_t& lp) {
    hp = pk_lohi(x0, x1);
    __nv_bfloat162 hb = *reinterpret_cast<__nv_bfloat162*>(&hp);
    lp = pk_lohi(x0 - __bfloat162float(hb.x), x1 - __bfloat162float(hb.y));
}
__device__ __forceinline__ float bf16_part(float x, int tau) {
    float h = __bfloat162float(__float2bfloat16(x));
    return tau ? (x - h) : h;
}
__device__ __forceinline__ void mma_bf16(float c[4], const uint32_t a[4], uint32_t b0, uint32_t b1) {
    asm volatile(
        "mma.sync.aligned.m16n8k16.row.col.f32.bf16.bf16.f32 "
        "{%0,%1,%2,%3},{%4,%5,%6,%7},{%8,%9},{%0,%1,%2,%3};"
        : "+f"(c[0]), "+f"(c[1]), "+f"(c[2]), "+f"(c[3])
        : "r"(a[0]), "r"(a[1]), "r"(a[2]), "r"(a[3]), "r"(b0), "r"(b1));
}

// 3-term stage: acc += A(16x64) * B(64x64); ONE LDS.128 per (j,t) feeds 3 mma
__device__ __forceinline__ void run_stage(float acc[8][4],
                                          const uint32_t ah[4][4], const uint32_t al[4][4],
                                          const uint4* __restrict__ B, int lane) {
    #pragma unroll
    for (int j = 0; j < 4; j++) {
        #pragma unroll
        for (int t = 0; t < 8; t++) {
            uint4 b = B[(j * 8 + t) * 32 + lane];
            mma_bf16(acc[t], ah[j], b.x, b.y);
            mma_bf16(acc[t], al[j], b.x, b.y);
            mma_bf16(acc[t], ah[j], b.z, b.w);
        }
    }
}

// ================= prep: fold + all B fragments =================
__global__ void prep_kernel(const float* __restrict__ fc1_w, const float* __restrict__ fc1_b,
                            const float* __restrict__ wq, const float* __restrict__ wk,
                            const float* __restrict__ wv,
                            const float* __restrict__ d2w, const float* __restrict__ g1w,
                            const float* __restrict__ g2w, const float* __restrict__ fc2w) {
    int e = blockIdx.x * 256 + threadIdx.x;
    if (e < 7 * 1024) {
        int mat = e >> 10, r = e & 1023;
        int j = r >> 8, t = (r >> 5) & 7, ln = r & 31;
        int k0 = 16 * j + (ln & 3) * 2, n = 8 * t + (ln >> 2);
        float w00, w01, w10, w11;
        if (mat < 3) {
            const float* Wsel = (mat == 0) ? wq : ((mat == 1) ? wk : wv);
            float a0 = 0.f, a1 = 0.f, a2 = 0.f, a3 = 0.f;
            #pragma unroll 8
            for (int m = 0; m < 64; m++) {
                float wm = Wsel[m * 64 + n];
                a0 = fmaf(fc1_w[k0 * 64 + m], wm, a0);
                a1 = fmaf(fc1_w[(k0 + 1) * 64 + m], wm, a1);
                a2 = fmaf(fc1_w[(k0 + 8) * 64 + m], wm, a2);
                a3 = fmaf(fc1_w[(k0 + 9) * 64 + m], wm, a3);
            }
            w00 = a0; w01 = a1; w10 = a2; w11 = a3;
        } else {
            const float* W = (mat == 3) ? d2w : ((mat == 4) ? g1w : ((mat == 5) ? g2w : fc2w));
            w00 = W[k0 * 64 + n]; w01 = W[(k0 + 1) * 64 + n];
            w10 = W[(k0 + 8) * 64 + n]; w11 = W[(k0 + 9) * 64 + n];
        }
        uint4 rr;
        rr.x = pk_lohi(bf16_part(w00, 0), bf16_part(w01, 0));
        rr.y = pk_lohi(bf16_part(w10, 0), bf16_part(w11, 0));
        rr.z = pk_lohi(bf16_part(w00, 1), bf16_part(w01, 1));
        rr.w = pk_lohi(bf16_part(w10, 1), bf16_part(w11, 1));
        g_frag[mat][r] = rr;
    } else if (e < 7 * 1024 + 192) {
        int o = e - 7 * 1024, w = o >> 6, f = o & 63;
        const float* Wsel = (w == 0) ? wq : ((w == 1) ? wk : wv);
        float acc = 0.f;
        #pragma unroll 8
        for (int m = 0; m < 64; m++) acc = fmaf(fc1_b[m], Wsel[m * 64 + f], acc);
        g_bf[w][f] = acc;
    }
}

// ================= qkv3: Q/XK/XV via mma =================
struct SQ { uint4 bf[3][1024]; float bias[3][64]; };

__global__ __launch_bounds__(256, 2) void qkv3_kernel(const float* __restrict__ features) {
    extern __shared__ __align__(16) unsigned char smraw[];
    SQ* S = reinterpret_cast<SQ*>(smraw);
    const int tid = threadIdx.x;
    {
        const uint4* src = &g_frag[0][0];
        uint4* dst = &S->bf[0][0];
        for (int i = tid; i < 3072; i += 256) dst[i] = src[i];
        for (int i = tid; i < 192; i += 256) S->bias[i >> 6][i & 63] = g_bf[i >> 6][i & 63];
    }
    __syncthreads();

    const int wid = tid >> 5, lane = tid & 31;
    const int r0 = lane >> 2, r1 = r0 + 8, cq = (lane & 3) * 2;
    const int m0 = blockIdx.x * 128 + wid * 16;

    uint32_t ah[4][4], al[4][4];
    const float* A0 = features + (size_t)(m0 + r0) * DM;
    const float* A1 = features + (size_t)(m0 + r1) * DM;
    #pragma unroll
    for (int j = 0; j < 4; j++) {
        int c = 16 * j + cq;
        float2 x00 = *(const float2*)(A0 + c);
        float2 x10 = *(const float2*)(A1 + c);
        float2 x01 = *(const float2*)(A0 + c + 8);
        float2 x11 = *(const float2*)(A1 + c + 8);
        spack(x00.x, x00.y, ah[j][0], al[j][0]);
        spack(x10.x, x10.y, ah[j][1], al[j][1]);
        spack(x01.x, x01.y, ah[j][2], al[j][2]);
        spack(x11.x, x11.y, ah[j][3], al[j][3]);
    }

    #pragma unroll
    for (int w = 0; w < 3; w++) {
        float acc[8][4];
        #pragma unroll
        for (int t = 0; t < 8; t++) { acc[t][0] = acc[t][1] = acc[t][2] = acc[t][3] = 0.f; }
        run_stage(acc, ah, al, &S->bf[w][0], lane);
        float* O = g_QKV[w];
        #pragma unroll
        for (int t = 0; t < 8; t++) {
            int c = 8 * t + cq;
            float b0 = S->bias[w][c], b1 = S->bias[w][c + 1];
            *(float2*)(O + (size_t)(m0 + r0) * DM + c) = make_float2(acc[t][0] + b0, acc[t][1] + b1);
            *(float2*)(O + (size_t)(m0 + r1) * DM + c) = make_float2(acc[t][2] + b0, acc[t][3] + b1);
        }
    }
}

// ================= fc2 via mma =================
struct SF { uint4 bf[1024]; float bias[64]; };

__global__ __launch_bounds__(256, 2) void fc2_kernel(const float* __restrict__ fc2b,
                                                     const float* __restrict__ features,
                                                     float* __restrict__ out) {
    extern __shared__ __align__(16) unsigned char smraw[];
    SF* S = reinterpret_cast<SF*>(smraw);
    const int tid = threadIdx.x;
    {
        const uint4* src = &g_frag[6][0];
        uint4* dst = &S->bf[0];
        for (int i = tid; i < 1024; i += 256) dst[i] = src[i];
        if (tid < 64) S->bias[tid] = fc2b[tid];
    }
    __syncthreads();

    const int wid = tid >> 5, lane = tid & 31;
    const int r0 = lane >> 2, r1 = r0 + 8, cq = (lane & 3) * 2;
    const int m0 = blockIdx.x * 128 + wid * 16;

    uint32_t ah[4][4], al[4][4];
    const float* A0 = g_res + (size_t)(m0 + r0) * DM;
    const float* A1 = g_res + (size_t)(m0 + r1) * DM;
    #pragma unroll
    for (int j = 0; j < 4; j++) {
        int c = 16 * j + cq;
        float2 x00 = *(const float2*)(A0 + c);
        float2 x10 = *(const float2*)(A1 + c);
        float2 x01 = *(const float2*)(A0 + c + 8);
        float2 x11 = *(const float2*)(A1 + c + 8);
        spack(x00.x, x00.y, ah[j][0], al[j][0]);
        spack(x10.x, x10.y, ah[j][1], al[j][1]);
        spack(x01.x, x01.y, ah[j][2], al[j][2]);
        spack(x11.x, x11.y, ah[j][3], al[j][3]);
    }
    float acc[8][4];
    #pragma unroll
    for (int t = 0; t < 8; t++) { acc[t][0] = acc[t][1] = acc[t][2] = acc[t][3] = 0.f; }
    run_stage(acc, ah, al, &S->bf[0], lane);
    #pragma unroll
    for (int t = 0; t < 8; t++) {
        int c = 8 * t + cq;
        float b0 = S->bias[c], b1 = S->bias[c + 1];
        float2 f0 = *(const float2*)(features + (size_t)(m0 + r0) * DM + c);
        float2 f1 = *(const float2*)(features + (size_t)(m0 + r1) * DM + c);
        *(float2*)(out + (size_t)(m0 + r0) * DM + c) = make_float2(acc[t][0] + b0 + f0.x, acc[t][1] + b1 + f0.y);
        *(float2*)(out + (size_t)(m0 + r1) * DM + c) = make_float2(acc[t][2] + b0 + f1.x, acc[t][3] + b1 + f1.y);
    }
}

// ================= main: fused per-neighbor transformer =================
struct SMemM {
    uint4 bf[3][1024];   // d2, g1, g2 (hi+lo packed)
    float d1[192];
    float bD1[64], bD2[64], bG1[64], bG2[64];
};

__global__ __launch_bounds__(256, 2) void main_kernel(
    const float* __restrict__ xyz, const int* __restrict__ knn,
    const float* __restrict__ d1w, const float* __restrict__ d1b,
    const float* __restrict__ d2b, const float* __restrict__ g1b,
    const float* __restrict__ g2b, float* __restrict__ out) {
    extern __shared__ __align__(16) unsigned char smraw[];
    SMemM* S = reinterpret_cast<SMemM*>(smraw);
    const int tid = threadIdx.x;
    {
        const uint4* src = &g_frag[3][0];
        uint4* dst = &S->bf[0][0];
        for (int i = tid; i < 3072; i += 256) dst[i] = src[i];
    }
    for (int i = tid; i < 192; i += 256) S->d1[i] = d1w[i];
    if (tid < 64) {
        S->bD1[tid] = d1b[tid]; S->bD2[tid] = d2b[tid];
        S->bG1[tid] = g1b[tid]; S->bG2[tid] = g2b[tid];
    }
    __syncthreads();

    const int wid = tid >> 5, lane = tid & 31;
    const int r0 = lane >> 2, r1 = r0 + 8;
    const int cq = (lane & 3) * 2;
    float* __restrict__ attn_out = out + (size_t)NPTS * DM;

    for (int m = blockIdx.x * 8 + wid; m < NPTS; m += gridDim.x * 8) {
        const int base = (m >> 13) * NN;
        const int i0 = knn[m * KNN + r0];
        const int i1 = knn[m * KNN + r1];
        const float cx = xyz[3 * m], cy = xyz[3 * m + 1], cz = xyz[3 * m + 2];
        const float* x0p = xyz + (size_t)(base + i0) * 3;
        const float* x1p = xyz + (size_t)(base + i1) * 3;
        const float rx0 = cx - x0p[0], ry0 = cy - x0p[1], rz0 = cz - x0p[2];
        const float rx1 = cx - x1p[0], ry1 = cy - x1p[1], rz1 = cz - x1p[2];

        uint32_t ah[4][4], al[4][4];
        // ---- t = relu(rel @ d1 + d1b) in frag layout ----
        #pragma unroll
        for (int j = 0; j < 4; j++) {
            #pragma unroll
            for (int half = 0; half < 2; half++) {
                int c = 16 * j + 8 * half + cq;
                float b0 = S->bD1[c], b1 = S->bD1[c + 1];
                float wx0 = S->d1[c], wy0 = S->d1[64 + c], wz0 = S->d1[128 + c];
                float wx1 = S->d1[c + 1], wy1 = S->d1[65 + c], wz1 = S->d1[129 + c];
                float t00 = fmaxf(fmaf(rz0, wz0, fmaf(ry0, wy0, fmaf(rx0, wx0, b0))), 0.f);
                float t01 = fmaxf(fmaf(rz0, wz1, fmaf(ry0, wy1, fmaf(rx0, wx1, b1))), 0.f);
                float t10 = fmaxf(fmaf(rz1, wz0, fmaf(ry1, wy0, fmaf(rx1, wx0, b0))), 0.f);
                float t11 = fmaxf(fmaf(rz1, wz1, fmaf(ry1, wy1, fmaf(rx1, wx1, b1))), 0.f);
                spack(t00, t01, ah[j][2 * half], al[j][2 * half]);
                spack(t10, t11, ah[j][2 * half + 1], al[j][2 * half + 1]);
            }
        }
        float acc[8][4];
        #pragma unroll
        for (int t = 0; t < 8; t++) { acc[t][0] = acc[t][1] = acc[t][2] = acc[t][3] = 0.f; }
        run_stage(acc, ah, al, &S->bf[0][0], lane);

        // ---- pos = D + d2b ----
        float pos[8][4];
        #pragma unroll
        for (int t = 0; t < 8; t++) {
            int c = 8 * t + cq;
            float b0 = S->bD2[c], b1 = S->bD2[c + 1];
            pos[t][0] = acc[t][0] + b0; pos[t][1] = acc[t][1] + b1;
            pos[t][2] = acc[t][2] + b0; pos[t][3] = acc[t][3] + b1;
        }

        // ---- h = q - k + pos ----
        {
            const float* Qrow = g_QKV[0] + (size_t)m * DM;
            const float* Kr0 = g_QKV[1] + (size_t)(base + i0) * DM;
            const float* Kr1 = g_QKV[1] + (size_t)(base + i1) * DM;
            #pragma unroll
            for (int j = 0; j < 4; j++) {
                #pragma unroll
                for (int half = 0; half < 2; half++) {
                    int t = 2 * j + half;
                    int c = 8 * t + cq;
                    float2 q2 = *(const float2*)(Qrow + c);
                    float2 k0 = *(const float2*)(Kr0 + c);
                    float2 k1 = *(const float2*)(Kr1 + c);
                    float h00 = q2.x - k0.x + pos[t][0];
                    float h01 = q2.y - k0.y + pos[t][1];
                    float h10 = q2.x - k1.x + pos[t][2];
                    float h11 = q2.y - k1.y + pos[t][3];
                    spack(h00, h01, ah[j][2 * half], al[j][2 * half]);
                    spack(h10, h11, ah[j][2 * half + 1], al[j][2 * half + 1]);
                }
            }
        }
        #pragma unroll
        for (int t = 0; t < 8; t++) { acc[t][0] = acc[t][1] = acc[t][2] = acc[t][3] = 0.f; }
        run_stage(acc, ah, al, &S->bf[1][0], lane);

        // ---- u = relu(D + g1b) ----
        #pragma unroll
        for (int j = 0; j < 4; j++) {
            #pragma unroll
            for (int half = 0; half < 2; half++) {
                int t = 2 * j + half;
                int c = 8 * t + cq;
                float b0 = S->bG1[c], b1 = S->bG1[c + 1];
                float u00 = fmaxf(acc[t][0] + b0, 0.f), u01 = fmaxf(acc[t][1] + b1, 0.f);
                float u10 = fmaxf(acc[t][2] + b0, 0.f), u11 = fmaxf(acc[t][3] + b1, 0.f);
                spack(u00, u01, ah[j][2 * half], al[j][2 * half]);
                spack(u10, u11, ah[j][2 * half + 1], al[j][2 * half + 1]);
            }
        }
        #pragma unroll
        for (int t = 0; t < 8; t++) { acc[t][0] = acc[t][1] = acc[t][2] = acc[t][3] = 0.f; }
        run_stage(acc, ah, al, &S->bf[2][0], lane);

        // ---- softmax over neighbors + outputs ----
        {
            const float* Vr0 = g_QKV[2] + (size_t)(base + i0) * DM;
            const float* Vr1 = g_QKV[2] + (size_t)(base + i1) * DM;
            float* ao = attn_out + (size_t)m * (KNN * DM);
            float* ro = g_res + (size_t)m * DM;
            #pragma unroll
            for (int t = 0; t < 8; t++) {
                int c = 8 * t + cq;
                float b0 = S->bG2[c], b1 = S->bG2[c + 1];
                float l00 = acc[t][0] + b0, l01 = acc[t][1] + b1;
                float l10 = acc[t][2] + b0, l11 = acc[t][3] + b1;
                float m0 = fmaxf(l00, l10), m1 = fmaxf(l01, l11);
                #pragma unroll
                for (int o = 4; o < 32; o <<= 1) {
                    m0 = fmaxf(m0, __shfl_xor_sync(0xffffffffu, m0, o));
                    m1 = fmaxf(m1, __shfl_xor_sync(0xffffffffu, m1, o));
                }
                float e00 = __expf((l00 - m0) * 0.125f), e10 = __expf((l10 - m0) * 0.125f);
                float e01 = __expf((l01 - m1) * 0.125f), e11 = __expf((l11 - m1) * 0.125f);
                float s0 = e00 + e10, s1 = e01 + e11;
                #pragma unroll
                for (int o = 4; o < 32; o <<= 1) {
                    s0 += __shfl_xor_sync(0xffffffffu, s0, o);
                    s1 += __shfl_xor_sync(0xffffffffu, s1, o);
                }
                float inv0 = 1.f / s0, inv1 = 1.f / s1;
                float a00 = e00 * inv0, a01 = e01 * inv1;
                float a10 = e10 * inv0, a11 = e11 * inv1;
                *(float2*)(ao + r0 * DM + c) = make_float2(a00, a01);
                *(float2*)(ao + r1 * DM + c) = make_float2(a10, a11);
                float2 v0 = *(const float2*)(Vr0 + c);
                float2 v1 = *(const float2*)(Vr1 + c);
                float rc0 = a00 * (v0.x + pos[t][0]) + a10 * (v1.x + pos[t][2]);
                float rc1 = a01 * (v0.y + pos[t][1]) + a11 * (v1.y + pos[t][3]);
                #pragma unroll
                for (int o = 4; o < 32; o <<= 1) {
                    rc0 += __shfl_xor_sync(0xffffffffu, rc0, o);
                    rc1 += __shfl_xor_sync(0xffffffffu, rc1, o);
                }
                if (lane < 4) *(float2*)(ro + c) = make_float2(rc0, rc1);
            }
        }
    }
}

// ================= launch =================
extern "C" void kernel_launch(void* const* d_in, const int* in_sizes, int n_in,
                              void* d_out, int out_size) {
    const float* xyz      = (const float*)d_in[0];
    const float* features = (const float*)d_in[1];
    const int*   knn      = (const int*)d_in[2];
    const float* fc1_w    = (const float*)d_in[3];
    const float* fc1_b    = (const float*)d_in[4];
    const float* fc2_w    = (const float*)d_in[5];
    const float* fc2_b    = (const float*)d_in[6];
    const float* d1_w     = (const float*)d_in[7];
    const float* d1_b     = (const float*)d_in[8];
    const float* d2_w     = (const float*)d_in[9];
    const float* d2_b     = (const float*)d_in[10];
    const float* g1_w     = (const float*)d_in[11];
    const float* g1_b     = (const float*)d_in[12];
    const float* g2_w     = (const float*)d_in[13];
    const float* g2_b     = (const float*)d_in[14];
    const float* wq       = (const float*)d_in[15];
    const float* wk       = (const float*)d_in[16];
    const float* wv       = (const float*)d_in[17];
    float* out = (float*)d_out;

    prep_kernel<<<29, 256>>>(fc1_w, fc1_b, wq, wk, wv, d2_w, g1_w, g2_w, fc2_w);

    cudaFuncSetAttribute(qkv3_kernel, cudaFuncAttributeMaxDynamicSharedMemorySize, (int)sizeof(SQ));
    qkv3_kernel<<<NPTS / 128, 256, sizeof(SQ)>>>(features);

    cudaFuncSetAttribute(main_kernel, cudaFuncAttributeMaxDynamicSharedMemorySize, (int)sizeof(SMemM));
    main_kernel<<<296, 256, sizeof(SMemM)>>>(xyz, knn, d1_w, d1_b, d2_b, g1_b, g2_b, out);

    cudaFuncSetAttribute(fc2_kernel, cudaFuncAttributeMaxDynamicSharedMemorySize, (int)sizeof(SF));
    fc2_kernel<<<NPTS / 128, 256, sizeof(SF)>>>(fc2_b, features, out);
}

// round 10
// speedup vs baseline: 3.4748x; 1.1827x over previous
#include <cuda_runtime.h>
#include <cuda_fp16.h>
#include <stdint.h>
#include <math.h>

#define NB 4
#define NN 8192
#define KNN 16
#define DM 64
#define NPTS (NB * NN)   // 32768

__device__ float g_QKV[3][(size_t)NPTS * DM];
__device__ float g_res[(size_t)NPTS * DM];
__device__ float g_bf[3][DM];
// frag store: [mat 0..6][1024] uint2 = fp16 B fragment (hi only)
// (mat: 0-2 folded fc1@{wq,wk,wv}, 3 d2, 4 g1, 5 g2, 6 fc2)
__device__ uint2 g_frag[7][1024];

// ---------------- fp16 helpers ----------------
// pack (lo, hi) floats into one f16x2 reg; first asm operand lands in UPPER half
__device__ __forceinline__ uint32_t pk_lohi(float lo, float hi) {
    uint32_t r;
    asm("cvt.rn.satfinite.f16x2.f32 %0, %1, %2;" : "=r"(r) : "f"(hi), "f"(lo));
    return r;
}
// split (x0,x1) into fp16 hi pair and fp16 lo-residual pair
__device__ __forceinline__ void spack(float x0, float x1, uint32_t& hp, uint32_t& lp) {
    hp = pk_lohi(x0, x1);
    __half2 h = *reinterpret_cast<__half2*>(&hp);
    lp = pk_lohi(x0 - __half2float(h.x), x1 - __half2float(h.y));
}
__device__ __forceinline__ void mma_f16(float c[4], const uint32_t a[4], uint32_t b0, uint32_t b1) {
    asm volatile(
        "mma.sync.aligned.m16n8k16.row.col.f32.f16.f16.f32 "
        "{%0,%1,%2,%3},{%4,%5,%6,%7},{%8,%9},{%0,%1,%2,%3};"
        : "+f"(c[0]), "+f"(c[1]), "+f"(c[2]), "+f"(c[3])
        : "r"(a[0]), "r"(a[1]), "r"(a[2]), "r"(a[3]), "r"(b0), "r"(b1));
}

// 2-term stage: acc += A(16x64) * B(64x64); ONE LDS.64 per (j,t) feeds 2 mma
__device__ __forceinline__ void run_stage(float acc[8][4],
                                          const uint32_t ah[4][4], const uint32_t al[4][4],
                                          const uint2* __restrict__ B, int lane) {
    #pragma unroll
    for (int j = 0; j < 4; j++) {
        #pragma unroll
        for (int t = 0; t < 8; t++) {
            uint2 b = B[(j * 8 + t) * 32 + lane];
            mma_f16(acc[t], ah[j], b.x, b.y);
            mma_f16(acc[t], al[j], b.x, b.y);
        }
    }
}

// ================= prep: fold + all B fragments =================
__global__ void prep_kernel(const float* __restrict__ fc1_w, const float* __restrict__ fc1_b,
                            const float* __restrict__ wq, const float* __restrict__ wk,
                            const float* __restrict__ wv,
                            const float* __restrict__ d2w, const float* __restrict__ g1w,
                            const float* __restrict__ g2w, const float* __restrict__ fc2w) {
    int e = blockIdx.x * 256 + threadIdx.x;
    if (e < 7 * 1024) {
        int mat = e >> 10, r = e & 1023;
        int j = r >> 8, t = (r >> 5) & 7, ln = r & 31;
        int k0 = 16 * j + (ln & 3) * 2, n = 8 * t + (ln >> 2);
        float w00, w01, w10, w11;
        if (mat < 3) {
            const float* Wsel = (mat == 0) ? wq : ((mat == 1) ? wk : wv);
            float a0 = 0.f, a1 = 0.f, a2 = 0.f, a3 = 0.f;
            #pragma unroll 8
            for (int m = 0; m < 64; m++) {
                float wm = Wsel[m * 64 + n];
                a0 = fmaf(fc1_w[k0 * 64 + m], wm, a0);
                a1 = fmaf(fc1_w[(k0 + 1) * 64 + m], wm, a1);
                a2 = fmaf(fc1_w[(k0 + 8) * 64 + m], wm, a2);
                a3 = fmaf(fc1_w[(k0 + 9) * 64 + m], wm, a3);
            }
            w00 = a0; w01 = a1; w10 = a2; w11 = a3;
        } else {
            const float* W = (mat == 3) ? d2w : ((mat == 4) ? g1w : ((mat == 5) ? g2w : fc2w));
            w00 = W[k0 * 64 + n]; w01 = W[(k0 + 1) * 64 + n];
            w10 = W[(k0 + 8) * 64 + n]; w11 = W[(k0 + 9) * 64 + n];
        }
        uint2 rr;
        rr.x = pk_lohi(w00, w01);
        rr.y = pk_lohi(w10, w11);
        g_frag[mat][r] = rr;
    } else if (e < 7 * 1024 + 192) {
        int o = e - 7 * 1024, w = o >> 6, f = o & 63;
        const float* Wsel = (w == 0) ? wq : ((w == 1) ? wk : wv);
        float acc = 0.f;
        #pragma unroll 8
        for (int m = 0; m < 64; m++) acc = fmaf(fc1_b[m], Wsel[m * 64 + f], acc);
        g_bf[w][f] = acc;
    }
}

// ================= qkv3: Q/XK/XV via mma =================
struct SQ { uint2 bf[3][1024]; float bias[3][64]; };

__global__ __launch_bounds__(256, 2) void qkv3_kernel(const float* __restrict__ features) {
    extern __shared__ __align__(16) unsigned char smraw[];
    SQ* S = reinterpret_cast<SQ*>(smraw);
    const int tid = threadIdx.x;
    {
        const uint4* src = (const uint4*)&g_frag[0][0];
        uint4* dst = (uint4*)&S->bf[0][0];
        for (int i = tid; i < 1536; i += 256) dst[i] = src[i];   // 3*1024 uint2 = 1536 uint4
        for (int i = tid; i < 192; i += 256) S->bias[i >> 6][i & 63] = g_bf[i >> 6][i & 63];
    }
    __syncthreads();

    const int wid = tid >> 5, lane = tid & 31;
    const int r0 = lane >> 2, r1 = r0 + 8, cq = (lane & 3) * 2;
    const int m0 = blockIdx.x * 128 + wid * 16;

    uint32_t ah[4][4], al[4][4];
    const float* A0 = features + (size_t)(m0 + r0) * DM;
    const float* A1 = features + (size_t)(m0 + r1) * DM;
    #pragma unroll
    for (int j = 0; j < 4; j++) {
        int c = 16 * j + cq;
        float2 x00 = *(const float2*)(A0 + c);
        float2 x10 = *(const float2*)(A1 + c);
        float2 x01 = *(const float2*)(A0 + c + 8);
        float2 x11 = *(const float2*)(A1 + c + 8);
        spack(x00.x, x00.y, ah[j][0], al[j][0]);
        spack(x10.x, x10.y, ah[j][1], al[j][1]);
        spack(x01.x, x01.y, ah[j][2], al[j][2]);
        spack(x11.x, x11.y, ah[j][3], al[j][3]);
    }

    #pragma unroll
    for (int w = 0; w < 3; w++) {
        float acc[8][4];
        #pragma unroll
        for (int t = 0; t < 8; t++) { acc[t][0] = acc[t][1] = acc[t][2] = acc[t][3] = 0.f; }
        run_stage(acc, ah, al, &S->bf[w][0], lane);
        float* O = g_QKV[w];
        #pragma unroll
        for (int t = 0; t < 8; t++) {
            int c = 8 * t + cq;
            float b0 = S->bias[w][c], b1 = S->bias[w][c + 1];
            *(float2*)(O + (size_t)(m0 + r0) * DM + c) = make_float2(acc[t][0] + b0, acc[t][1] + b1);
            *(float2*)(O + (size_t)(m0 + r1) * DM + c) = make_float2(acc[t][2] + b0, acc[t][3] + b1);
        }
    }
}

// ================= fc2 via mma =================
struct SF { uint2 bf[1024]; float bias[64]; };

__global__ __launch_bounds__(256, 2) void fc2_kernel(const float* __restrict__ fc2b,
                                                     const float* __restrict__ features,
                                                     float* __restrict__ out) {
    extern __shared__ __align__(16) unsigned char smraw[];
    SF* S = reinterpret_cast<SF*>(smraw);
    const int tid = threadIdx.x;
    {
        const uint4* src = (const uint4*)&g_frag[6][0];
        uint4* dst = (uint4*)&S->bf[0];
        for (int i = tid; i < 512; i += 256) dst[i] = src[i];   // 1024 uint2 = 512 uint4
        if (tid < 64) S->bias[tid] = fc2b[tid];
    }
    __syncthreads();

    const int wid = tid >> 5, lane = tid & 31;
    const int r0 = lane >> 2, r1 = r0 + 8, cq = (lane & 3) * 2;
    const int m0 = blockIdx.x * 128 + wid * 16;

    uint32_t ah[4][4], al[4][4];
    const float* A0 = g_res + (size_t)(m0 + r0) * DM;
    const float* A1 = g_res + (size_t)(m0 + r1) * DM;
    #pragma unroll
    for (int j = 0; j < 4; j++) {
        int c = 16 * j + cq;
        float2 x00 = *(const float2*)(A0 + c);
        float2 x10 = *(const float2*)(A1 + c);
        float2 x01 = *(const float2*)(A0 + c + 8);
        float2 x11 = *(const float2*)(A1 + c + 8);
        spack(x00.x, x00.y, ah[j][0], al[j][0]);
        spack(x10.x, x10.y, ah[j][1], al[j][1]);
        spack(x01.x, x01.y, ah[j][2], al[j][2]);
        spack(x11.x, x11.y, ah[j][3], al[j][3]);
    }
    float acc[8][4];
    #pragma unroll
    for (int t = 0; t < 8; t++) { acc[t][0] = acc[t][1] = acc[t][2] = acc[t][3] = 0.f; }
    run_stage(acc, ah, al, &S->bf[0], lane);
    #pragma unroll
    for (int t = 0; t < 8; t++) {
        int c = 8 * t + cq;
        float b0 = S->bias[c], b1 = S->bias[c + 1];
        float2 f0 = *(const float2*)(features + (size_t)(m0 + r0) * DM + c);
        float2 f1 = *(const float2*)(features + (size_t)(m0 + r1) * DM + c);
        *(float2*)(out + (size_t)(m0 + r0) * DM + c) = make_float2(acc[t][0] + b0 + f0.x, acc[t][1] + b1 + f0.y);
        *(float2*)(out + (size_t)(m0 + r1) * DM + c) = make_float2(acc[t][2] + b0 + f1.x, acc[t][3] + b1 + f1.y);
    }
}

// ================= main: fused per-neighbor transformer =================
struct SMemM {
    uint2 bf[3][1024];   // d2, g1, g2 (fp16 hi)
    float d1[192];
    float bD1[64], bD2[64], bG1[64], bG2[64];
};

__global__ __launch_bounds__(256, 2) void main_kernel(
    const float* __restrict__ xyz, const int* __restrict__ knn,
    const float* __restrict__ d1w, const float* __restrict__ d1b,
    const float* __restrict__ d2b, const float* __restrict__ g1b,
    const float* __restrict__ g2b, float* __restrict__ out) {
    extern __shared__ __align__(16) unsigned char smraw[];
    SMemM* S = reinterpret_cast<SMemM*>(smraw);
    const int tid = threadIdx.x;
    {
        const uint4* src = (const uint4*)&g_frag[3][0];
        uint4* dst = (uint4*)&S->bf[0][0];
        for (int i = tid; i < 1536; i += 256) dst[i] = src[i];   // 3*1024 uint2 = 1536 uint4
    }
    for (int i = tid; i < 192; i += 256) S->d1[i] = d1w[i];
    if (tid < 64) {
        S->bD1[tid] = d1b[tid]; S->bD2[tid] = d2b[tid];
        S->bG1[tid] = g1b[tid]; S->bG2[tid] = g2b[tid];
    }
    __syncthreads();

    const int wid = tid >> 5, lane = tid & 31;
    const int r0 = lane >> 2, r1 = r0 + 8;
    const int cq = (lane & 3) * 2;
    float* __restrict__ attn_out = out + (size_t)NPTS * DM;

    for (int m = blockIdx.x * 8 + wid; m < NPTS; m += gridDim.x * 8) {
        const int base = (m >> 13) * NN;
        const int i0 = knn[m * KNN + r0];
        const int i1 = knn[m * KNN + r1];
        const float cx = xyz[3 * m], cy = xyz[3 * m + 1], cz = xyz[3 * m + 2];
        const float* x0p = xyz + (size_t)(base + i0) * 3;
        const float* x1p = xyz + (size_t)(base + i1) * 3;
        const float rx0 = cx - x0p[0], ry0 = cy - x0p[1], rz0 = cz - x0p[2];
        const float rx1 = cx - x1p[0], ry1 = cy - x1p[1], rz1 = cz - x1p[2];

        uint32_t ah[4][4], al[4][4];
        // ---- t = relu(rel @ d1 + d1b) in frag layout ----
        #pragma unroll
        for (int j = 0; j < 4; j++) {
            #pragma unroll
            for (int half = 0; half < 2; half++) {
                int c = 16 * j + 8 * half + cq;
                float b0 = S->bD1[c], b1 = S->bD1[c + 1];
                float wx0 = S->d1[c], wy0 = S->d1[64 + c], wz0 = S->d1[128 + c];
                float wx1 = S->d1[c + 1], wy1 = S->d1[65 + c], wz1 = S->d1[129 + c];
                float t00 = fmaxf(fmaf(rz0, wz0, fmaf(ry0, wy0, fmaf(rx0, wx0, b0))), 0.f);
                float t01 = fmaxf(fmaf(rz0, wz1, fmaf(ry0, wy1, fmaf(rx0, wx1, b1))), 0.f);
                float t10 = fmaxf(fmaf(rz1, wz0, fmaf(ry1, wy0, fmaf(rx1, wx0, b0))), 0.f);
                float t11 = fmaxf(fmaf(rz1, wz1, fmaf(ry1, wy1, fmaf(rx1, wx1, b1))), 0.f);
                spack(t00, t01, ah[j][2 * half], al[j][2 * half]);
                spack(t10, t11, ah[j][2 * half + 1], al[j][2 * half + 1]);
            }
        }
        float acc[8][4];
        #pragma unroll
        for (int t = 0; t < 8; t++) { acc[t][0] = acc[t][1] = acc[t][2] = acc[t][3] = 0.f; }
        run_stage(acc, ah, al, &S->bf[0][0], lane);

        // ---- pos = D + d2b ----
        float pos[8][4];
        #pragma unroll
        for (int t = 0; t < 8; t++) {
            int c = 8 * t + cq;
            float b0 = S->bD2[c], b1 = S->bD2[c + 1];
            pos[t][0] = acc[t][0] + b0; pos[t][1] = acc[t][1] + b1;
            pos[t][2] = acc[t][2] + b0; pos[t][3] = acc[t][3] + b1;
        }

        // ---- h = q - k + pos ----
        {
            const float* Qrow = g_QKV[0] + (size_t)m * DM;
            const float* Kr0 = g_QKV[1] + (size_t)(base + i0) * DM;
            const float* Kr1 = g_QKV[1] + (size_t)(base + i1) * DM;
            #pragma unroll
            for (int j = 0; j < 4; j++) {
                #pragma unroll
                for (int half = 0; half < 2; half++) {
                    int t = 2 * j + half;
                    int c = 8 * t + cq;
                    float2 q2 = *(const float2*)(Qrow + c);
                    float2 k0 = *(const float2*)(Kr0 + c);
                    float2 k1 = *(const float2*)(Kr1 + c);
                    float h00 = q2.x - k0.x + pos[t][0];
                    float h01 = q2.y - k0.y + pos[t][1];
                    float h10 = q2.x - k1.x + pos[t][2];
                    float h11 = q2.y - k1.y + pos[t][3];
                    spack(h00, h01, ah[j][2 * half], al[j][2 * half]);
                    spack(h10, h11, ah[j][2 * half + 1], al[j][2 * half + 1]);
                }
            }
        }
        #pragma unroll
        for (int t = 0; t < 8; t++) { acc[t][0] = acc[t][1] = acc[t][2] = acc[t][3] = 0.f; }
        run_stage(acc, ah, al, &S->bf[1][0], lane);

        // ---- u = relu(D + g1b) ----
        #pragma unroll
        for (int j = 0; j < 4; j++) {
            #pragma unroll
            for (int half = 0; half < 2; half++) {
                int t = 2 * j + half;
                int c = 8 * t + cq;
                float b0 = S->bG1[c], b1 = S->bG1[c + 1];
                float u00 = fmaxf(acc[t][0] + b0, 0.f), u01 = fmaxf(acc[t][1] + b1, 0.f);
                float u10 = fmaxf(acc[t][2] + b0, 0.f), u11 = fmaxf(acc[t][3] + b1, 0.f);
                spack(u00, u01, ah[j][2 * half], al[j][2 * half]);
                spack(u10, u11, ah[j][2 * half + 1], al[j][2 * half + 1]);
            }
        }
        #pragma unroll
        for (int t = 0; t < 8; t++) { acc[t][0] = acc[t][1] = acc[t][2] = acc[t][3] = 0.f; }
        run_stage(acc, ah, al, &S->bf[2][0], lane);

        // ---- softmax over neighbors + outputs ----
        {
            const float* Vr0 = g_QKV[2] + (size_t)(base + i0) * DM;
            const float* Vr1 = g_QKV[2] + (size_t)(base + i1) * DM;
            float* ao = attn_out + (size_t)m * (KNN * DM);
            float* ro = g_res + (size_t)m * DM;
            #pragma unroll
            for (int t = 0; t < 8; t++) {
                int c = 8 * t + cq;
                float b0 = S->bG2[c], b1 = S->bG2[c + 1];
                float l00 = acc[t][0] + b0, l01 = acc[t][1] + b1;
                float l10 = acc[t][2] + b0, l11 = acc[t][3] + b1;
                float m0 = fmaxf(l00, l10), m1 = fmaxf(l01, l11);
                #pragma unroll
                for (int o = 4; o < 32; o <<= 1) {
                    m0 = fmaxf(m0, __shfl_xor_sync(0xffffffffu, m0, o));
                    m1 = fmaxf(m1, __shfl_xor_sync(0xffffffffu, m1, o));
                }
                float e00 = __expf((l00 - m0) * 0.125f), e10 = __expf((l10 - m0) * 0.125f);
                float e01 = __expf((l01 - m1) * 0.125f), e11 = __expf((l11 - m1) * 0.125f);
                float s0 = e00 + e10, s1 = e01 + e11;
                #pragma unroll
                for (int o = 4; o < 32; o <<= 1) {
                    s0 += __shfl_xor_sync(0xffffffffu, s0, o);
                    s1 += __shfl_xor_sync(0xffffffffu, s1, o);
                }
                float inv0 = 1.f / s0, inv1 = 1.f / s1;
                float a00 = e00 * inv0, a01 = e01 * inv1;
                float a10 = e10 * inv0, a11 = e11 * inv1;
                *(float2*)(ao + r0 * DM + c) = make_float2(a00, a01);
                *(float2*)(ao + r1 * DM + c) = make_float2(a10, a11);
                float2 v0 = *(const float2*)(Vr0 + c);
                float2 v1 = *(const float2*)(Vr1 + c);
                float rc0 = a00 * (v0.x + pos[t][0]) + a10 * (v1.x + pos[t][2]);
                float rc1 = a01 * (v0.y + pos[t][1]) + a11 * (v1.y + pos[t][3]);
                #pragma unroll
                for (int o = 4; o < 32; o <<= 1) {
                    rc0 += __shfl_xor_sync(0xffffffffu, rc0, o);
                    rc1 += __shfl_xor_sync(0xffffffffu, rc1, o);
                }
                if (lane < 4) *(float2*)(ro + c) = make_float2(rc0, rc1);
            }
        }
    }
}

// ================= launch =================
extern "C" void kernel_launch(void* const* d_in, const int* in_sizes, int n_in,
                              void* d_out, int out_size) {
    const float* xyz      = (const float*)d_in[0];
    const float* features = (const float*)d_in[1];
    const int*   knn      = (const int*)d_in[2];
    const float* fc1_w    = (const float*)d_in[3];
    const float* fc1_b    = (const float*)d_in[4];
    const float* fc2_w    = (const float*)d_in[5];
    const float* fc2_b    = (const float*)d_in[6];
    const float* d1_w     = (const float*)d_in[7];
    const float* d1_b     = (const float*)d_in[8];
    const float* d2_w     = (const float*)d_in[9];
    const float* d2_b     = (const float*)d_in[10];
    const float* g1_w     = (const float*)d_in[11];
    const float* g1_b     = (const float*)d_in[12];
    const float* g2_w     = (const float*)d_in[13];
    const float* g2_b     = (const float*)d_in[14];
    const float* wq       = (const float*)d_in[15];
    const float* wk       = (const float*)d_in[16];
    const float* wv       = (const float*)d_in[17];
    float* out = (float*)d_out;

    prep_kernel<<<29, 256>>>(fc1_w, fc1_b, wq, wk, wv, d2_w, g1_w, g2_w, fc2_w);

    cudaFuncSetAttribute(qkv3_kernel, cudaFuncAttributeMaxDynamicSharedMemorySize, (int)sizeof(SQ));
    qkv3_kernel<<<NPTS / 128, 256, sizeof(SQ)>>>(features);

    cudaFuncSetAttribute(main_kernel, cudaFuncAttributeMaxDynamicSharedMemorySize, (int)sizeof(SMemM));
    main_kernel<<<296, 256, sizeof(SMemM)>>>(xyz, knn, d1_w, d1_b, d2_b, g1_b, g2_b, out);

    cudaFuncSetAttribute(fc2_kernel, cudaFuncAttributeMaxDynamicSharedMemorySize, (int)sizeof(SF));
    fc2_kernel<<<NPTS / 128, 256, sizeof(SF)>>>(fc2_b, features, out);
}

// round 12
// speedup vs baseline: 3.6743x; 1.0574x over previous
#include <cuda_runtime.h>
#include <cuda_fp16.h>
#include <stdint.h>
#include <math.h>

#define NB 4
#define NN 8192
#define KNN 16
#define DM 64
#define NPTS (NB * NN)   // 32768

__device__ float g_QKV[3][(size_t)NPTS * DM];
__device__ float g_res[(size_t)NPTS * DM];
__device__ float g_bf[3][DM];
// frag store: [mat 0..6][1024] uint2 = fp16 B fragment
// (mat: 0-2 folded fc1@{wq,wk,wv}, 3 d2, 4 g1, 5 g2, 6 fc2)
__device__ uint2 g_frag[7][1024];

// ---------------- fp16 helpers ----------------
__device__ __forceinline__ uint32_t pk_lohi(float lo, float hi) {
    uint32_t r;
    asm("cvt.rn.satfinite.f16x2.f32 %0, %1, %2;" : "=r"(r) : "f"(hi), "f"(lo));
    return r;
}
__device__ __forceinline__ void spack(float x0, float x1, uint32_t& hp, uint32_t& lp) {
    hp = pk_lohi(x0, x1);
    __half2 h = *reinterpret_cast<__half2*>(&hp);
    lp = pk_lohi(x0 - __half2float(h.x), x1 - __half2float(h.y));
}
__device__ __forceinline__ void mma_f16(float c[4], const uint32_t a[4], uint32_t b0, uint32_t b1) {
    asm volatile(
        "mma.sync.aligned.m16n8k16.row.col.f32.f16.f16.f32 "
        "{%0,%1,%2,%3},{%4,%5,%6,%7},{%8,%9},{%0,%1,%2,%3};"
        : "+f"(c[0]), "+f"(c[1]), "+f"(c[2]), "+f"(c[3])
        : "r"(a[0]), "r"(a[1]), "r"(a[2]), "r"(a[3]), "r"(b0), "r"(b1));
}

// 2-term stage: acc += A(16x64) * B(64x64); ONE LDS.64 per (j,t) feeds 2 mma
__device__ __forceinline__ void run_stage(float acc[8][4],
                                          const uint32_t ah[4][4], const uint32_t al[4][4],
                                          const uint2* __restrict__ B, int lane) {
    #pragma unroll
    for (int j = 0; j < 4; j++) {
        #pragma unroll
        for (int t = 0; t < 8; t++) {
            uint2 b = B[(j * 8 + t) * 32 + lane];
            mma_f16(acc[t], ah[j], b.x, b.y);
            mma_f16(acc[t], al[j], b.x, b.y);
        }
    }
}

// ================= prep: fold + all B fragments =================
__global__ void prep_kernel(const float* __restrict__ fc1_w, const float* __restrict__ fc1_b,
                            const float* __restrict__ wq, const float* __restrict__ wk,
                            const float* __restrict__ wv,
                            const float* __restrict__ d2w, const float* __restrict__ g1w,
                            const float* __restrict__ g2w, const float* __restrict__ fc2w) {
    int e = blockIdx.x * 256 + threadIdx.x;
    if (e < 7 * 1024) {
        int mat = e >> 10, r = e & 1023;
        int j = r >> 8, t = (r >> 5) & 7, ln = r & 31;
        int k0 = 16 * j + (ln & 3) * 2, n = 8 * t + (ln >> 2);
        float w00, w01, w10, w11;
        if (mat < 3) {
            const float* Wsel = (mat == 0) ? wq : ((mat == 1) ? wk : wv);
            float a0 = 0.f, a1 = 0.f, a2 = 0.f, a3 = 0.f;
            #pragma unroll 8
            for (int m = 0; m < 64; m++) {
                float wm = Wsel[m * 64 + n];
                a0 = fmaf(fc1_w[k0 * 64 + m], wm, a0);
                a1 = fmaf(fc1_w[(k0 + 1) * 64 + m], wm, a1);
                a2 = fmaf(fc1_w[(k0 + 8) * 64 + m], wm, a2);
                a3 = fmaf(fc1_w[(k0 + 9) * 64 + m], wm, a3);
            }
            w00 = a0; w01 = a1; w10 = a2; w11 = a3;
        } else {
            const float* W = (mat == 3) ? d2w : ((mat == 4) ? g1w : ((mat == 5) ? g2w : fc2w));
            w00 = W[k0 * 64 + n]; w01 = W[(k0 + 1) * 64 + n];
            w10 = W[(k0 + 8) * 64 + n]; w11 = W[(k0 + 9) * 64 + n];
        }
        uint2 rr;
        rr.x = pk_lohi(w00, w01);
        rr.y = pk_lohi(w10, w11);
        g_frag[mat][r] = rr;
    } else if (e < 7 * 1024 + 192) {
        int o = e - 7 * 1024, w = o >> 6, f = o & 63;
        const float* Wsel = (w == 0) ? wq : ((w == 1) ? wk : wv);
        float acc = 0.f;
        #pragma unroll 8
        for (int m = 0; m < 64; m++) acc = fmaf(fc1_b[m], Wsel[m * 64 + f], acc);
        g_bf[w][f] = acc;
    }
}

// ================= qkv3: Q/XK/XV via mma =================
struct SQ { uint2 bf[3][1024]; float bias[3][64]; };

__global__ __launch_bounds__(256, 2) void qkv3_kernel(const float* __restrict__ features) {
    extern __shared__ __align__(16) unsigned char smraw[];
    SQ* S = reinterpret_cast<SQ*>(smraw);
    const int tid = threadIdx.x;
    {
        const uint4* src = (const uint4*)&g_frag[0][0];
        uint4* dst = (uint4*)&S->bf[0][0];
        for (int i = tid; i < 1536; i += 256) dst[i] = src[i];
        for (int i = tid; i < 192; i += 256) S->bias[i >> 6][i & 63] = g_bf[i >> 6][i & 63];
    }
    __syncthreads();

    const int wid = tid >> 5, lane = tid & 31;
    const int r0 = lane >> 2, r1 = r0 + 8, cq = (lane & 3) * 2;
    const int m0 = blockIdx.x * 128 + wid * 16;

    uint32_t ah[4][4], al[4][4];
    const float* A0 = features + (size_t)(m0 + r0) * DM;
    const float* A1 = features + (size_t)(m0 + r1) * DM;
    #pragma unroll
    for (int j = 0; j < 4; j++) {
        int c = 16 * j + cq;
        float2 x00 = *(const float2*)(A0 + c);
        float2 x10 = *(const float2*)(A1 + c);
        float2 x01 = *(const float2*)(A0 + c + 8);
        float2 x11 = *(const float2*)(A1 + c + 8);
        spack(x00.x, x00.y, ah[j][0], al[j][0]);
        spack(x10.x, x10.y, ah[j][1], al[j][1]);
        spack(x01.x, x01.y, ah[j][2], al[j][2]);
        spack(x11.x, x11.y, ah[j][3], al[j][3]);
    }

    #pragma unroll
    for (int w = 0; w < 3; w++) {
        float acc[8][4];
        #pragma unroll
        for (int t = 0; t < 8; t++) { acc[t][0] = acc[t][1] = acc[t][2] = acc[t][3] = 0.f; }
        run_stage(acc, ah, al, &S->bf[w][0], lane);
        float* O = g_QKV[w];
        #pragma unroll
        for (int t = 0; t < 8; t++) {
            int c = 8 * t + cq;
            float b0 = S->bias[w][c], b1 = S->bias[w][c + 1];
            *(float2*)(O + (size_t)(m0 + r0) * DM + c) = make_float2(acc[t][0] + b0, acc[t][1] + b1);
            *(float2*)(O + (size_t)(m0 + r1) * DM + c) = make_float2(acc[t][2] + b0, acc[t][3] + b1);
        }
    }
}

// ================= fc2 via mma =================
struct SF { uint2 bf[1024]; float bias[64]; };

__global__ __launch_bounds__(256, 2) void fc2_kernel(const float* __restrict__ fc2b,
                                                     const float* __restrict__ features,
                                                     float* __restrict__ out) {
    extern __shared__ __align__(16) unsigned char smraw[];
    SF* S = reinterpret_cast<SF*>(smraw);
    const int tid = threadIdx.x;
    {
        const uint4* src = (const uint4*)&g_frag[6][0];
        uint4* dst = (uint4*)&S->bf[0];
        for (int i = tid; i < 512; i += 256) dst[i] = src[i];
        if (tid < 64) S->bias[tid] = fc2b[tid];
    }
    __syncthreads();

    const int wid = tid >> 5, lane = tid & 31;
    const int r0 = lane >> 2, r1 = r0 + 8, cq = (lane & 3) * 2;
    const int m0 = blockIdx.x * 128 + wid * 16;

    uint32_t ah[4][4], al[4][4];
    const float* A0 = g_res + (size_t)(m0 + r0) * DM;
    const float* A1 = g_res + (size_t)(m0 + r1) * DM;
    #pragma unroll
    for (int j = 0; j < 4; j++) {
        int c = 16 * j + cq;
        float2 x00 = *(const float2*)(A0 + c);
        float2 x10 = *(const float2*)(A1 + c);
        float2 x01 = *(const float2*)(A0 + c + 8);
        float2 x11 = *(const float2*)(A1 + c + 8);
        spack(x00.x, x00.y, ah[j][0], al[j][0]);
        spack(x10.x, x10.y, ah[j][1], al[j][1]);
        spack(x01.x, x01.y, ah[j][2], al[j][2]);
        spack(x11.x, x11.y, ah[j][3], al[j][3]);
    }
    float acc[8][4];
    #pragma unroll
    for (int t = 0; t < 8; t++) { acc[t][0] = acc[t][1] = acc[t][2] = acc[t][3] = 0.f; }
    run_stage(acc, ah, al, &S->bf[0], lane);
    #pragma unroll
    for (int t = 0; t < 8; t++) {
        int c = 8 * t + cq;
        float b0 = S->bias[c], b1 = S->bias[c + 1];
        float2 f0 = *(const float2*)(features + (size_t)(m0 + r0) * DM + c);
        float2 f1 = *(const float2*)(features + (size_t)(m0 + r1) * DM + c);
        *(float2*)(out + (size_t)(m0 + r0) * DM + c) = make_float2(acc[t][0] + b0 + f0.x, acc[t][1] + b1 + f0.y);
        *(float2*)(out + (size_t)(m0 + r1) * DM + c) = make_float2(acc[t][2] + b0 + f1.x, acc[t][3] + b1 + f1.y);
    }
}

// ================= main: fused per-neighbor transformer =================
struct SMemM {
    uint2 bf[3][1024];   // d2, g1, g2 (fp16)
    float d1[192];
    float bD1[64], bD2[64], bG1[64], bG2[64];
};

__global__ __launch_bounds__(256, 2) void main_kernel(
    const float* __restrict__ xyz, const int* __restrict__ knn,
    const float* __restrict__ d1w, const float* __restrict__ d1b,
    const float* __restrict__ d2b, const float* __restrict__ g1b,
    const float* __restrict__ g2b, float* __restrict__ out) {
    extern __shared__ __align__(16) unsigned char smraw[];
    SMemM* S = reinterpret_cast<SMemM*>(smraw);
    const int tid = threadIdx.x;
    {
        const uint4* src = (const uint4*)&g_frag[3][0];
        uint4* dst = (uint4*)&S->bf[0][0];
        for (int i = tid; i < 1536; i += 256) dst[i] = src[i];
    }
    for (int i = tid; i < 192; i += 256) S->d1[i] = d1w[i];
    if (tid < 64) {
        S->bD1[tid] = d1b[tid]; S->bD2[tid] = d2b[tid];
        S->bG1[tid] = g1b[tid]; S->bG2[tid] = g2b[tid];
    }
    __syncthreads();

    const int wid = tid >> 5, lane = tid & 31;
    const int r0 = lane >> 2, r1 = r0 + 8;
    const int cq = (lane & 3) * 2;
    float* __restrict__ attn_out = out + (size_t)NPTS * DM;
    const int stride = gridDim.x * 8;

    int m = blockIdx.x * 8 + wid;
    // ---- initial prefetch: indices + xyz for first iteration ----
    int pi0 = 0, pi1 = 0;
    float pxc = 0, pyc = 0, pzc = 0;
    float pn0x = 0, pn0y = 0, pn0z = 0, pn1x = 0, pn1y = 0, pn1z = 0;
    if (m < NPTS) {
        const int base = (m >> 13) * NN;
        pi0 = knn[m * KNN + r0];
        pi1 = knn[m * KNN + r1];
        pxc = xyz[3 * m]; pyc = xyz[3 * m + 1]; pzc = xyz[3 * m + 2];
        const float* n0 = xyz + (size_t)(base + pi0) * 3;
        const float* n1 = xyz + (size_t)(base + pi1) * 3;
        pn0x = n0[0]; pn0y = n0[1]; pn0z = n0[2];
        pn1x = n1[0]; pn1y = n1[1]; pn1z = n1[2];
    }

    for (; m < NPTS; m += stride) {
        const int base = (m >> 13) * NN;
        const int i0 = pi0, i1 = pi1;
        const float rx0 = pxc - pn0x, ry0 = pyc - pn0y, rz0 = pzc - pn0z;
        const float rx1 = pxc - pn1x, ry1 = pyc - pn1y, rz1 = pzc - pn1z;
        const int mn = m + stride;
        // prefetch next iteration's knn rows (2-hop chain starts now)
        if (mn < NPTS) {
            pi0 = knn[mn * KNN + r0];
            pi1 = knn[mn * KNN + r1];
        }

        // issue Q-row and K-row loads up front; consumed after stage 1
        const float* Qrow = g_QKV[0] + (size_t)m * DM;
        const float* Kr0p = g_QKV[1] + (size_t)(base + i0) * DM;
        const float* Kr1p = g_QKV[1] + (size_t)(base + i1) * DM;
        float2 qb[8], kb0[8], kb1[8];
        #pragma unroll
        for (int t = 0; t < 8; t++) {
            qb[t]  = *(const float2*)(Qrow + 8 * t + cq);
            kb0[t] = *(const float2*)(Kr0p + 8 * t + cq);
            kb1[t] = *(const float2*)(Kr1p + 8 * t + cq);
        }

        uint32_t ah[4][4], al[4][4];
        // ---- t = relu(rel @ d1 + d1b) in frag layout ----
        #pragma unroll
        for (int j = 0; j < 4; j++) {
            #pragma unroll
            for (int half = 0; half < 2; half++) {
                int c = 16 * j + 8 * half + cq;
                float b0 = S->bD1[c], b1 = S->bD1[c + 1];
                float wx0 = S->d1[c], wy0 = S->d1[64 + c], wz0 = S->d1[128 + c];
                float wx1 = S->d1[c + 1], wy1 = S->d1[65 + c], wz1 = S->d1[129 + c];
                float t00 = fmaxf(fmaf(rz0, wz0, fmaf(ry0, wy0, fmaf(rx0, wx0, b0))), 0.f);
                float t01 = fmaxf(fmaf(rz0, wz1, fmaf(ry0, wy1, fmaf(rx0, wx1, b1))), 0.f);
                float t10 = fmaxf(fmaf(rz1, wz0, fmaf(ry1, wy0, fmaf(rx1, wx0, b0))), 0.f);
                float t11 = fmaxf(fmaf(rz1, wz1, fmaf(ry1, wy1, fmaf(rx1, wx1, b1))), 0.f);
                spack(t00, t01, ah[j][2 * half], al[j][2 * half]);
                spack(t10, t11, ah[j][2 * half + 1], al[j][2 * half + 1]);
            }
        }
        float acc[8][4];
        #pragma unroll
        for (int t = 0; t < 8; t++) { acc[t][0] = acc[t][1] = acc[t][2] = acc[t][3] = 0.f; }
        run_stage(acc, ah, al, &S->bf[0][0], lane);

        // ---- pos = D + d2b ----
        float pos[8][4];
        #pragma unroll
        for (int t = 0; t < 8; t++) {
            int c = 8 * t + cq;
            float b0 = S->bD2[c], b1 = S->bD2[c + 1];
            pos[t][0] = acc[t][0] + b0; pos[t][1] = acc[t][1] + b1;
            pos[t][2] = acc[t][2] + b0; pos[t][3] = acc[t][3] + b1;
        }

        // ---- h = q - k + pos (q/k already in registers) ----
        #pragma unroll
        for (int j = 0; j < 4; j++) {
            #pragma unroll
            for (int half = 0; half < 2; half++) {
                int t = 2 * j + half;
                float h00 = qb[t].x - kb0[t].x + pos[t][0];
                float h01 = qb[t].y - kb0[t].y + pos[t][1];
                float h10 = qb[t].x - kb1[t].x + pos[t][2];
                float h11 = qb[t].y - kb1[t].y + pos[t][3];
                spack(h00, h01, ah[j][2 * half], al[j][2 * half]);
                spack(h10, h11, ah[j][2 * half + 1], al[j][2 * half + 1]);
            }
        }
        #pragma unroll
        for (int t = 0; t < 8; t++) { acc[t][0] = acc[t][1] = acc[t][2] = acc[t][3] = 0.f; }
        run_stage(acc, ah, al, &S->bf[1][0], lane);

        // ---- u = relu(D + g1b) ----
        #pragma unroll
        for (int j = 0; j < 4; j++) {
            #pragma unroll
            for (int half = 0; half < 2; half++) {
                int t = 2 * j + half;
                int c = 8 * t + cq;
                float b0 = S->bG1[c], b1 = S->bG1[c + 1];
                float u00 = fmaxf(acc[t][0] + b0, 0.f), u01 = fmaxf(acc[t][1] + b1, 0.f);
                float u10 = fmaxf(acc[t][2] + b0, 0.f), u11 = fmaxf(acc[t][3] + b1, 0.f);
                spack(u00, u01, ah[j][2 * half], al[j][2 * half]);
                spack(u10, u11, ah[j][2 * half + 1], al[j][2 * half + 1]);
            }
        }
        #pragma unroll
        for (int t = 0; t < 8; t++) { acc[t][0] = acc[t][1] = acc[t][2] = acc[t][3] = 0.f; }
        run_stage(acc, ah, al, &S->bf[2][0], lane);

        // ---- prefetch next iteration's xyz (uses new pi0/pi1) ----
        if (mn < NPTS) {
            const int nbase = (mn >> 13) * NN;
            pxc = xyz[3 * mn]; pyc = xyz[3 * mn + 1]; pzc = xyz[3 * mn + 2];
            const float* n0 = xyz + (size_t)(nbase + pi0) * 3;
            const float* n1 = xyz + (size_t)(nbase + pi1) * 3;
            pn0x = n0[0]; pn0y = n0[1]; pn0z = n0[2];
            pn1x = n1[0]; pn1y = n1[1]; pn1z = n1[2];
        }

        // ---- softmax over neighbors (no max subtraction; fp32 exp safe) ----
        {
            const float* Vr0 = g_QKV[2] + (size_t)(base + i0) * DM;
            const float* Vr1 = g_QKV[2] + (size_t)(base + i1) * DM;
            float* ao = attn_out + (size_t)m * (KNN * DM);
            float* ro = g_res + (size_t)m * DM;
            #pragma unroll
            for (int t = 0; t < 8; t++) {
                int c = 8 * t + cq;
                float b0 = S->bG2[c], b1 = S->bG2[c + 1];
                float e00 = __expf((acc[t][0] + b0) * 0.125f);
                float e01 = __expf((acc[t][1] + b1) * 0.125f);
                float e10 = __expf((acc[t][2] + b0) * 0.125f);
                float e11 = __expf((acc[t][3] + b1) * 0.125f);
                float s0 = e00 + e10, s1 = e01 + e11;
                #pragma unroll
                for (int o = 4; o < 32; o <<= 1) {
                    s0 += __shfl_xor_sync(0xffffffffu, s0, o);
                    s1 += __shfl_xor_sync(0xffffffffu, s1, o);
                }
                float inv0 = 1.f / s0, inv1 = 1.f / s1;
                float a00 = e00 * inv0, a01 = e01 * inv1;
                float a10 = e10 * inv0, a11 = e11 * inv1;
                *(float2*)(ao + r0 * DM + c) = make_float2(a00, a01);
                *(float2*)(ao + r1 * DM + c) = make_float2(a10, a11);
                float2 v0 = *(const float2*)(Vr0 + c);
                float2 v1 = *(const float2*)(Vr1 + c);
                float rc0 = a00 * (v0.x + pos[t][0]) + a10 * (v1.x + pos[t][2]);
                float rc1 = a01 * (v0.y + pos[t][1]) + a11 * (v1.y + pos[t][3]);
                #pragma unroll
                for (int o = 4; o < 32; o <<= 1) {
                    rc0 += __shfl_xor_sync(0xffffffffu, rc0, o);
                    rc1 += __shfl_xor_sync(0xffffffffu, rc1, o);
                }
                if (lane < 4) *(float2*)(ro + c) = make_float2(rc0, rc1);
            }
        }
    }
}

// ================= launch =================
extern "C" void kernel_launch(void* const* d_in, const int* in_sizes, int n_in,
                              void* d_out, int out_size) {
    const float* xyz      = (const float*)d_in[0];
    const float* features = (const float*)d_in[1];
    const int*   knn      = (const int*)d_in[2];
    const float* fc1_w    = (const float*)d_in[3];
    const float* fc1_b    = (const float*)d_in[4];
    const float* fc2_w    = (const float*)d_in[5];
    const float* fc2_b    = (const float*)d_in[6];
    const float* d1_w     = (const float*)d_in[7];
    const float* d1_b     = (const float*)d_in[8];
    const float* d2_w     = (const float*)d_in[9];
    const float* d2_b     = (const float*)d_in[10];
    const float* g1_w     = (const float*)d_in[11];
    const float* g1_b     = (const float*)d_in[12];
    const float* g2_w     = (const float*)d_in[13];
    const float* g2_b     = (const float*)d_in[14];
    const float* wq       = (const float*)d_in[15];
    const float* wk       = (const float*)d_in[16];
    const float* wv       = (const float*)d_in[17];
    float* out = (float*)d_out;

    prep_kernel<<<29, 256>>>(fc1_w, fc1_b, wq, wk, wv, d2_w, g1_w, g2_w, fc2_w);

    cudaFuncSetAttribute(qkv3_kernel, cudaFuncAttributeMaxDynamicSharedMemorySize, (int)sizeof(SQ));
    qkv3_kernel<<<NPTS / 128, 256, sizeof(SQ)>>>(features);

    cudaFuncSetAttribute(main_kernel, cudaFuncAttributeMaxDynamicSharedMemorySize, (int)sizeof(SMemM));
    main_kernel<<<296, 256, sizeof(SMemM)>>>(xyz, knn, d1_w, d1_b, d2_b, g1_b, g2_b, out);

    cudaFuncSetAttribute(fc2_kernel, cudaFuncAttributeMaxDynamicSharedMemorySize, (int)sizeof(SF));
    fc2_kernel<<<NPTS / 128, 256, sizeof(SF)>>>(fc2_b, features, out);
}